// round 5
// baseline (speedup 1.0000x reference)
#include <cuda_runtime.h>
#include <math.h>

#define BB 128
#define TT 256
#define FF 64
#define HH 512
#define G4 2048   // 4*H
#define NBLK 128  // persistent LSTM grid size

// ---------------- packed f32x2 helpers (sm_100+) ----------------
__device__ __forceinline__ unsigned long long pack2(float x, float y) {
    unsigned long long r;
    asm("mov.b64 %0, {%1, %2};"
        : "=l"(r) : "r"(__float_as_uint(x)), "r"(__float_as_uint(y)));
    return r;
}
__device__ __forceinline__ void fma2(unsigned long long& d,
                                     unsigned long long a,
                                     unsigned long long b) {
    asm("fma.rn.f32x2 %0, %1, %2, %3;" : "=l"(d) : "l"(a), "l"(b), "l"(d));
}
__device__ __forceinline__ float2 unpack2(unsigned long long v) {
    unsigned lo, hi;
    asm("mov.b64 {%0, %1}, %2;" : "=r"(lo), "=r"(hi) : "l"(v));
    return make_float2(__uint_as_float(lo), __uint_as_float(hi));
}

// ---------------- scratch (device globals; no allocation) ----------------
__device__ float g_h[BB * TT * HH];
__device__ float g_seq[BB * TT * HH];
__device__ float g_xg[BB * TT * G4];
__device__ float g_hA[BB * HH], g_hB[BB * HH];
__device__ float g_ln[BB * HH];
__device__ float g_d2[BB * (HH / 2)];
__device__ unsigned g_bar_count = 0;
__device__ unsigned g_bar_gen = 0;

// ---------------- software grid barrier ----------------
__device__ __forceinline__ void grid_bar() {
    __syncthreads();
    if (threadIdx.x == 0) {
        __threadfence();
        unsigned gen = *((volatile unsigned*)&g_bar_gen);
        if (atomicAdd(&g_bar_count, 1u) == NBLK - 1) {
            g_bar_count = 0;
            __threadfence();
            atomicAdd(&g_bar_gen, 1u);
        } else {
            while (*((volatile unsigned*)&g_bar_gen) == gen) {}
            __threadfence();
        }
    }
    __syncthreads();
}

// ---------------- dense1 + spectral-norm scale ----------------
__global__ void dense1_norm(const float* __restrict__ x,
                            const float* __restrict__ W1,
                            const float* __restrict__ b1) {
    __shared__ float xs[16][FF];
    __shared__ float hs[16][HH];
    const int tid = threadIdx.x;
    const int m0 = blockIdx.x * 16;

    for (int i = tid; i < 16 * FF; i += 256) {
        int r = i / FF, k = i % FF;
        xs[r][k] = x[(m0 + r) * FF + k];
    }
    __syncthreads();

    const int c0 = tid * 2;
    float acc0[16], acc1[16];
#pragma unroll
    for (int r = 0; r < 16; r++) { acc0[r] = 0.f; acc1[r] = 0.f; }

    for (int k = 0; k < FF; k++) {
        float w0 = W1[k * HH + c0];
        float w1 = W1[k * HH + c0 + 1];
#pragma unroll
        for (int r = 0; r < 16; r++) {
            float xv = xs[r][k];
            acc0[r] += xv * w0;
            acc1[r] += xv * w1;
        }
    }
    float bb0 = b1[c0], bb1 = b1[c0 + 1];
#pragma unroll
    for (int r = 0; r < 16; r++) {
        hs[r][c0]     = acc0[r] + bb0;
        hs[r][c0 + 1] = acc1[r] + bb1;
    }
    __syncthreads();

    int wid = tid >> 5, lane = tid & 31;
#pragma unroll
    for (int rr = 0; rr < 2; rr++) {
        int r = wid * 2 + rr;
        float ss = 0.f;
        for (int c = lane; c < HH; c += 32) { float v = hs[r][c]; ss += v * v; }
#pragma unroll
        for (int o = 16; o; o >>= 1) ss += __shfl_xor_sync(0xffffffffu, ss, o);
        float scale = sqrtf((float)HH) / fmaxf(sqrtf(ss), 1e-12f);
        for (int c = lane; c < HH; c += 32)
            g_h[(m0 + r) * HH + c] = hs[r][c] * scale;
    }
}

// ---------------- xg GEMM (f32x2, double-buffered regs) ----------------
// 128x128 tile, 256 threads, 8x8 per-thread tile as 4 row-pairs x 8 cols
__global__ void __launch_bounds__(256) gemm_xg(int src,
                                               const float* __restrict__ Wx,
                                               const float* __restrict__ bias) {
    const float* __restrict__ A = src ? g_seq : g_h;
    __shared__ float As[16 * 128];  // [k][m]
    __shared__ float Bs[16 * 128];  // [k][n]
    const int tid = threadIdx.x;
    const int tx = tid & 15, ty = tid >> 4;
    const int n0 = blockIdx.x * 128;
    const int m0 = blockIdx.y * 128;

    const int lm = tid >> 1;            // 0..127
    const int lk = (tid & 1) * 8;       // 0 or 8
    const int bn = (tid & 31) * 4;      // 0..124
    const int bk = tid >> 5;            // 0..7

    unsigned long long acc[4][8];
#pragma unroll
    for (int i = 0; i < 4; i++)
#pragma unroll
        for (int j = 0; j < 8; j++) acc[i][j] = 0ull;

    // initial prefetch (kc = 0)
    float4 ra0 = *(const float4*)&A[(m0 + lm) * HH + lk];
    float4 ra1 = *(const float4*)&A[(m0 + lm) * HH + lk + 4];
    float4 rb0 = *(const float4*)&Wx[bk * G4 + n0 + bn];
    float4 rb1 = *(const float4*)&Wx[(bk + 8) * G4 + n0 + bn];

    for (int kc = 0; kc < HH; kc += 16) {
        As[(lk + 0) * 128 + lm] = ra0.x;
        As[(lk + 1) * 128 + lm] = ra0.y;
        As[(lk + 2) * 128 + lm] = ra0.z;
        As[(lk + 3) * 128 + lm] = ra0.w;
        As[(lk + 4) * 128 + lm] = ra1.x;
        As[(lk + 5) * 128 + lm] = ra1.y;
        As[(lk + 6) * 128 + lm] = ra1.z;
        As[(lk + 7) * 128 + lm] = ra1.w;
        *(float4*)&Bs[bk * 128 + bn] = rb0;
        *(float4*)&Bs[(bk + 8) * 128 + bn] = rb1;
        __syncthreads();

        if (kc + 16 < HH) {
            ra0 = *(const float4*)&A[(m0 + lm) * HH + kc + 16 + lk];
            ra1 = *(const float4*)&A[(m0 + lm) * HH + kc + 16 + lk + 4];
            rb0 = *(const float4*)&Wx[(kc + 16 + bk) * G4 + n0 + bn];
            rb1 = *(const float4*)&Wx[(kc + 16 + bk + 8) * G4 + n0 + bn];
        }

#pragma unroll
        for (int k = 0; k < 16; k++) {
            // row pairs come packed straight out of SMEM
            ulonglong2 pa01 = *(const ulonglong2*)&As[k * 128 + ty * 4];
            ulonglong2 pa23 = *(const ulonglong2*)&As[k * 128 + ty * 4 + 64];
            float4 b0 = *(const float4*)&Bs[k * 128 + tx * 4];
            float4 b1 = *(const float4*)&Bs[k * 128 + tx * 4 + 64];
            unsigned long long pb[8];
            pb[0] = pack2(b0.x, b0.x); pb[1] = pack2(b0.y, b0.y);
            pb[2] = pack2(b0.z, b0.z); pb[3] = pack2(b0.w, b0.w);
            pb[4] = pack2(b1.x, b1.x); pb[5] = pack2(b1.y, b1.y);
            pb[6] = pack2(b1.z, b1.z); pb[7] = pack2(b1.w, b1.w);
            unsigned long long pa[4] = {pa01.x, pa01.y, pa23.x, pa23.y};
#pragma unroll
            for (int i = 0; i < 4; i++)
#pragma unroll
                for (int j = 0; j < 8; j++) fma2(acc[i][j], pa[i], pb[j]);
        }
        __syncthreads();
    }

    float4 bia0 = *(const float4*)&bias[n0 + tx * 4];
    float4 bia1 = *(const float4*)&bias[n0 + tx * 4 + 64];
    float bl[8] = {bia0.x, bia0.y, bia0.z, bia0.w, bia1.x, bia1.y, bia1.z, bia1.w};

#pragma unroll
    for (int ip = 0; ip < 4; ip++) {
        int rlo = m0 + (ip >> 1) * 64 + ty * 4 + (ip & 1) * 2;
        int rhi = rlo + 1;
        float lo[8], hi[8];
#pragma unroll
        for (int j = 0; j < 8; j++) {
            float2 v = unpack2(acc[ip][j]);
            lo[j] = v.x + bl[j];
            hi[j] = v.y + bl[j];
        }
        *(float4*)&g_xg[(size_t)rlo * G4 + n0 + tx * 4] =
            make_float4(lo[0], lo[1], lo[2], lo[3]);
        *(float4*)&g_xg[(size_t)rlo * G4 + n0 + tx * 4 + 64] =
            make_float4(lo[4], lo[5], lo[6], lo[7]);
        *(float4*)&g_xg[(size_t)rhi * G4 + n0 + tx * 4] =
            make_float4(hi[0], hi[1], hi[2], hi[3]);
        *(float4*)&g_xg[(size_t)rhi * G4 + n0 + tx * 4 + 64] =
            make_float4(hi[4], hi[5], hi[6], hi[7]);
    }
}

// ---------------- zero initial LSTM hidden state ----------------
__global__ void zero_state() {
    int i = blockIdx.x * 256 + threadIdx.x;
    if (i < BB * HH) g_hA[i] = 0.f;
}

// ---------------- persistent fused LSTM (f32x2 inner loop) ----------------
#define SMEM_LSTM ((512 * 64 + 32 * 512 + 32 * 64 + 32 * 16) * 4)

__global__ void __launch_bounds__(256, 1)
lstm_persist(const float* __restrict__ Wh, int layer) {
    extern __shared__ float sm[];
    float* Whs = sm;                       // [512][64]
    float* As  = Whs + 512 * 64;           // [32][512]
    float* Gs  = As + 32 * 512;            // [32][64]
    float* cs  = Gs + 32 * 64;             // [32][16]

    const int tid = threadIdx.x;
    const int b0 = blockIdx.x * 32;
    const int j0 = blockIdx.y * 16;

    for (int i = tid; i < 512 * 64; i += 256) {
        int k = i >> 6, c = i & 63;
        Whs[i] = Wh[k * G4 + (c >> 4) * HH + j0 + (c & 15)];
    }
    for (int i = tid; i < 512; i += 256) cs[i] = 0.f;
    __syncthreads();

    const int c0 = (tid & 15) * 4;      // gate-col within 64
    const int r0 = (tid >> 4) * 2;      // batch row pair within 32

    for (int t = 0; t < TT; t++) {
        const float* __restrict__ hprev = (t & 1) ? g_hB : g_hA;
        float* __restrict__ hnext = (t & 1) ? g_hA : g_hB;

        for (int i = tid * 4; i < 32 * 512; i += 256 * 4)
            *(float4*)&As[i] =
                *(const float4*)&hprev[((b0 + (i >> 9)) << 9) + (i & 511)];
        __syncthreads();

        unsigned long long a00 = 0ull, a01 = 0ull, a10 = 0ull, a11 = 0ull;
        const float* A0 = &As[r0 * 512];
        const float* A1 = &As[(r0 + 1) * 512];
#pragma unroll 8
        for (int k = 0; k < 512; k++) {
            float v0 = A0[k], v1 = A1[k];
            unsigned long long pa0 = pack2(v0, v0);
            unsigned long long pa1 = pack2(v1, v1);
            ulonglong2 b2 = *(const ulonglong2*)&Whs[k * 64 + c0];
            fma2(a00, pa0, b2.x); fma2(a01, pa0, b2.y);
            fma2(a10, pa1, b2.x); fma2(a11, pa1, b2.y);
        }
        float2 u00 = unpack2(a00), u01 = unpack2(a01);
        float2 u10 = unpack2(a10), u11 = unpack2(a11);
        *(float4*)&Gs[r0 * 64 + c0]       = make_float4(u00.x, u00.y, u01.x, u01.y);
        *(float4*)&Gs[(r0 + 1) * 64 + c0] = make_float4(u10.x, u10.y, u11.x, u11.y);
        __syncthreads();

#pragma unroll
        for (int p = tid; p < 512; p += 256) {
            int rr = p >> 4, jj = p & 15;
            int b = b0 + rr, j = j0 + jj;
            const float* __restrict__ xg = &g_xg[(size_t)(b * TT + t) * G4 + j];
            float iv = Gs[rr * 64 + jj]      + xg[0];
            float fv = Gs[rr * 64 + 16 + jj] + xg[512];
            float cv = Gs[rr * 64 + 32 + jj] + xg[1024];
            float ov = Gs[rr * 64 + 48 + jj] + xg[1536];
            iv = 1.f / (1.f + __expf(-iv));
            fv = 1.f / (1.f + __expf(-fv));
            ov = 1.f / (1.f + __expf(-ov));
            cv = tanhf(cv);
            float c = fv * cs[p] + iv * cv;
            cs[p] = c;
            float h = ov * tanhf(c);
            hnext[b * HH + j] = h;
            if (layer == 0) g_seq[(size_t)(b * TT + t) * HH + j] = h;
        }

        if (t < TT - 1) grid_bar();
    }
}

// ---------------- layernorm (eps=1e-3) ----------------
__global__ void layernorm(const float* __restrict__ gamma,
                          const float* __restrict__ beta) {
    const int b = blockIdx.x, tid = threadIdx.x;
    const float* __restrict__ h = &g_hA[b * HH];
    __shared__ float red[8];
    __shared__ float bc_mu, bc_rs;

    float s = 0.f;
    for (int j = tid; j < HH; j += 256) s += h[j];
#pragma unroll
    for (int o = 16; o; o >>= 1) s += __shfl_xor_sync(0xffffffffu, s, o);
    if ((tid & 31) == 0) red[tid >> 5] = s;
    __syncthreads();
    if (tid == 0) {
        float tsum = 0.f;
        for (int i = 0; i < 8; i++) tsum += red[i];
        bc_mu = tsum / (float)HH;
    }
    __syncthreads();
    float mu = bc_mu;

    float v = 0.f;
    for (int j = tid; j < HH; j += 256) { float d = h[j] - mu; v += d * d; }
#pragma unroll
    for (int o = 16; o; o >>= 1) v += __shfl_xor_sync(0xffffffffu, v, o);
    __syncthreads();
    if ((tid & 31) == 0) red[tid >> 5] = v;
    __syncthreads();
    if (tid == 0) {
        float tsum = 0.f;
        for (int i = 0; i < 8; i++) tsum += red[i];
        bc_rs = rsqrtf(tsum / (float)HH + 1e-3f);
    }
    __syncthreads();
    float rs = bc_rs;

    for (int j = tid; j < HH; j += 256)
        g_ln[b * HH + j] = (h[j] - mu) * rs * gamma[j] + beta[j];
}

// ---------------- dense2 + relu ----------------
__global__ void dense2(const float* __restrict__ W2, const float* __restrict__ b2) {
    const int b = blockIdx.x, c = threadIdx.x;
    const float* __restrict__ h = &g_ln[b * HH];
    float s = b2[c];
    for (int k = 0; k < HH; k++) s += h[k] * W2[k * 256 + c];
    g_d2[b * 256 + c] = fmaxf(s, 0.f);
}

// ---------------- dense3 ----------------
__global__ void dense3(const float* __restrict__ W3, const float* __restrict__ b3,
                       float* __restrict__ out) {
    const int b = blockIdx.x, tid = threadIdx.x;
    float s = g_d2[b * 256 + tid] * W3[tid];
#pragma unroll
    for (int o = 16; o; o >>= 1) s += __shfl_xor_sync(0xffffffffu, s, o);
    __shared__ float red[8];
    if ((tid & 31) == 0) red[tid >> 5] = s;
    __syncthreads();
    if (tid == 0) {
        float tsum = 0.f;
        for (int i = 0; i < 8; i++) tsum += red[i];
        out[b] = tsum + b3[0];
    }
}

// ---------------- launch ----------------
extern "C" void kernel_launch(void* const* d_in, const int* in_sizes, int n_in,
                              void* d_out, int out_size) {
    const float* x     = (const float*)d_in[0];
    const float* W1    = (const float*)d_in[1];
    const float* b1    = (const float*)d_in[2];
    const float* Wx1   = (const float*)d_in[3];
    const float* Wh1   = (const float*)d_in[4];
    const float* bl1   = (const float*)d_in[5];
    const float* Wx2   = (const float*)d_in[6];
    const float* Wh2   = (const float*)d_in[7];
    const float* bl2   = (const float*)d_in[8];
    const float* gamma = (const float*)d_in[9];
    const float* beta  = (const float*)d_in[10];
    const float* W2    = (const float*)d_in[11];
    const float* b2    = (const float*)d_in[12];
    const float* W3    = (const float*)d_in[13];
    const float* b3    = (const float*)d_in[14];
    float* out = (float*)d_out;

    static int smem_set = 0;
    if (!smem_set) {
        cudaFuncSetAttribute(lstm_persist,
                             cudaFuncAttributeMaxDynamicSharedMemorySize,
                             SMEM_LSTM);
        smem_set = 1;
    }

    dense1_norm<<<(BB * TT) / 16, 256>>>(x, W1, b1);

    gemm_xg<<<dim3(G4 / 128, (BB * TT) / 128), 256>>>(0, Wx1, bl1);
    zero_state<<<(BB * HH + 255) / 256, 256>>>();
    lstm_persist<<<dim3(4, 32), 256, SMEM_LSTM>>>(Wh1, 0);

    gemm_xg<<<dim3(G4 / 128, (BB * TT) / 128), 256>>>(1, Wx2, bl2);
    zero_state<<<(BB * HH + 255) / 256, 256>>>();
    lstm_persist<<<dim3(4, 32), 256, SMEM_LSTM>>>(Wh2, 1);

    layernorm<<<BB, 256>>>(gamma, beta);
    dense2<<<BB, 256>>>(W2, b2);
    dense3<<<BB, 256>>>(W3, b3, out);
}

// round 7
// speedup vs baseline: 1.8266x; 1.8266x over previous
#include <cuda_runtime.h>
#include <cuda_bf16.h>
#include <math.h>
#include <stdint.h>

#define BB 128
#define TT 256
#define FF 64
#define HH 512
#define G4 2048
#define NBLK 128  // persistent LSTM grid

// ---------------- mma.sync bf16 helper (arch-generic, sm_80+) ----------------
__device__ __forceinline__ void mma_bf16(float* d, const uint32_t* a, const uint32_t* b) {
    asm volatile(
        "mma.sync.aligned.m16n8k16.row.col.f32.bf16.bf16.f32 "
        "{%0,%1,%2,%3}, {%4,%5,%6,%7}, {%8,%9}, {%0,%1,%2,%3};"
        : "+f"(d[0]), "+f"(d[1]), "+f"(d[2]), "+f"(d[3])
        : "r"(a[0]), "r"(a[1]), "r"(a[2]), "r"(a[3]), "r"(b[0]), "r"(b[1]));
}

__device__ __forceinline__ void bsplit(float w, __nv_bfloat16* hi, __nv_bfloat16* lo) {
    __nv_bfloat16 h = __float2bfloat16(w);
    *hi = h;
    *lo = __float2bfloat16(w - __bfloat162float(h));
}

// ---------------- scratch (device globals; no allocation) ----------------
__device__ __nv_bfloat16 g_hh[BB * TT * HH], g_hl[BB * TT * HH];   // dense1 out splits
__device__ __nv_bfloat16 g_sh[BB * TT * HH], g_sl[BB * TT * HH];   // lstm1 seq splits
__device__ __nv_bfloat16 g_Wxh[2][G4 * HH], g_Wxl[2][G4 * HH];     // Wx splits, [n][k]
__device__ float g_xg[(size_t)BB * TT * G4];                       // input-gate precompute
__device__ __nv_bfloat16 g_hpA[BB * HH], g_hpB[BB * HH];           // h hi ping-pong
__device__ __nv_bfloat16 g_lpA[BB * HH], g_lpB[BB * HH];           // h lo ping-pong
__device__ float g_hfin[BB * HH];
__device__ float g_ln[BB * HH];
__device__ float g_d2[BB * (HH / 2)];
__device__ unsigned g_bar_count = 0;
__device__ unsigned g_bar_gen = 0;

// ---------------- software grid barrier (NBLK co-resident blocks) ----------
__device__ __forceinline__ void grid_bar() {
    __syncthreads();
    if (threadIdx.x == 0) {
        __threadfence();
        unsigned gen = *((volatile unsigned*)&g_bar_gen);
        if (atomicAdd(&g_bar_count, 1u) == NBLK - 1) {
            g_bar_count = 0;
            __threadfence();
            atomicAdd(&g_bar_gen, 1u);
        } else {
            while (*((volatile unsigned*)&g_bar_gen) == gen) {}
            __threadfence();
        }
    }
    __syncthreads();
}

// ---------------- dense1 + L2-norm scale (writes bf16 splits) ----------------
__global__ void dense1_norm(const float* __restrict__ x, const float* __restrict__ W1,
                            const float* __restrict__ b1) {
    __shared__ float xs[16][FF];
    __shared__ float hs[16][HH];
    const int tid = threadIdx.x;
    const int m0 = blockIdx.x * 16;
    for (int i = tid; i < 16 * FF; i += 256)
        xs[i / FF][i % FF] = x[(m0 + i / FF) * FF + i % FF];
    __syncthreads();
    const int c0 = tid * 2;
    float a0[16], a1[16];
#pragma unroll
    for (int r = 0; r < 16; r++) { a0[r] = 0.f; a1[r] = 0.f; }
    for (int k = 0; k < FF; k++) {
        float w0 = W1[k * HH + c0], w1 = W1[k * HH + c0 + 1];
#pragma unroll
        for (int r = 0; r < 16; r++) { float xv = xs[r][k]; a0[r] += xv * w0; a1[r] += xv * w1; }
    }
    float bb0 = b1[c0], bb1 = b1[c0 + 1];
#pragma unroll
    for (int r = 0; r < 16; r++) { hs[r][c0] = a0[r] + bb0; hs[r][c0 + 1] = a1[r] + bb1; }
    __syncthreads();
    int wid = tid >> 5, lane = tid & 31;
#pragma unroll
    for (int rr = 0; rr < 2; rr++) {
        int r = wid * 2 + rr;
        float ss = 0.f;
        for (int c = lane; c < HH; c += 32) { float v = hs[r][c]; ss += v * v; }
#pragma unroll
        for (int o = 16; o; o >>= 1) ss += __shfl_xor_sync(0xffffffffu, ss, o);
        float sc = sqrtf((float)HH) / fmaxf(sqrtf(ss), 1e-12f);
        for (int c = lane; c < HH; c += 32) {
            float v = hs[r][c] * sc;
            __nv_bfloat16 vh, vl;
            bsplit(v, &vh, &vl);
            g_hh[(size_t)(m0 + r) * HH + c] = vh;
            g_hl[(size_t)(m0 + r) * HH + c] = vl;
        }
    }
}

// ---------------- Wx -> transposed bf16 splits [n][k] ----------------
__global__ void convW(const float* __restrict__ W, int layer) {
    int i = blockIdx.x * 256 + threadIdx.x;
    if (i < HH * G4) {
        int k = i / G4, n = i % G4;
        __nv_bfloat16 h_, l_;
        bsplit(W[i], &h_, &l_);
        g_Wxh[layer][(size_t)n * HH + k] = h_;
        g_Wxl[layer][(size_t)n * HH + k] = l_;
    }
}

// ---------------- xg GEMM: bf16-split mma.sync ----------------
// block 128(M)x128(N), 256 thr, 8 warps as 4(M)x2(N), warp tile 32x64
__global__ void __launch_bounds__(256) gemm_xg(int layer, const float* __restrict__ bias) {
    const __nv_bfloat16* __restrict__ Ah = layer ? g_sh : g_hh;
    const __nv_bfloat16* __restrict__ Al = layer ? g_sl : g_hl;
    const __nv_bfloat16* __restrict__ Bh = g_Wxh[layer];
    const __nv_bfloat16* __restrict__ Bl = g_Wxl[layer];

    __shared__ __align__(16) uint8_t sm[4 * 128 * 48];  // Ah|Al|Bh|Bl, 48B row stride
    const int tid = threadIdx.x;
    const int lane = tid & 31, wid = tid >> 5;
    const int n0 = blockIdx.x * 128, m0 = blockIdx.y * 128;
    const int m_off = (wid >> 1) * 32, n_off = (wid & 1) * 64;
    const int lr = lane >> 2, lc = (lane & 3) * 2;

    float acc[2][8][4];
#pragma unroll
    for (int i = 0; i < 2; i++)
#pragma unroll
        for (int j = 0; j < 8; j++)
#pragma unroll
            for (int q = 0; q < 4; q++) acc[i][j][q] = 0.f;

    const int row = tid >> 1, half = tid & 1;
    const __nv_bfloat16* pAh = Ah + (size_t)(m0 + row) * HH + half * 8;
    const __nv_bfloat16* pAl = Al + (size_t)(m0 + row) * HH + half * 8;
    const __nv_bfloat16* pBh = Bh + (size_t)(n0 + row) * HH + half * 8;
    const __nv_bfloat16* pBl = Bl + (size_t)(n0 + row) * HH + half * 8;
    uint8_t* sA_h = sm + row * 48 + half * 16;
    uint8_t* sA_l = sA_h + 6144;
    uint8_t* sB_h = sA_h + 12288;
    uint8_t* sB_l = sA_h + 18432;

    uint4 rAh = *(const uint4*)pAh;
    uint4 rAl = *(const uint4*)pAl;
    uint4 rBh = *(const uint4*)pBh;
    uint4 rBl = *(const uint4*)pBl;

    for (int kc = 0; kc < HH; kc += 16) {
        *(uint4*)sA_h = rAh;
        *(uint4*)sA_l = rAl;
        *(uint4*)sB_h = rBh;
        *(uint4*)sB_l = rBl;
        __syncthreads();
        if (kc + 16 < HH) {
            rAh = *(const uint4*)(pAh + kc + 16);
            rAl = *(const uint4*)(pAl + kc + 16);
            rBh = *(const uint4*)(pBh + kc + 16);
            rBl = *(const uint4*)(pBl + kc + 16);
        }
        uint32_t afh[2][4], afl[2][4], bfh[8][2], bfl[8][2];
#pragma unroll
        for (int mi = 0; mi < 2; mi++) {
            int r0 = m_off + mi * 16 + lr;
            afh[mi][0] = *(const uint32_t*)(sm + r0 * 48 + lc * 2);
            afh[mi][1] = *(const uint32_t*)(sm + (r0 + 8) * 48 + lc * 2);
            afh[mi][2] = *(const uint32_t*)(sm + r0 * 48 + (lc + 8) * 2);
            afh[mi][3] = *(const uint32_t*)(sm + (r0 + 8) * 48 + (lc + 8) * 2);
            afl[mi][0] = *(const uint32_t*)(sm + 6144 + r0 * 48 + lc * 2);
            afl[mi][1] = *(const uint32_t*)(sm + 6144 + (r0 + 8) * 48 + lc * 2);
            afl[mi][2] = *(const uint32_t*)(sm + 6144 + r0 * 48 + (lc + 8) * 2);
            afl[mi][3] = *(const uint32_t*)(sm + 6144 + (r0 + 8) * 48 + (lc + 8) * 2);
        }
#pragma unroll
        for (int nf = 0; nf < 8; nf++) {
            int n = n_off + nf * 8 + lr;
            bfh[nf][0] = *(const uint32_t*)(sm + 12288 + n * 48 + lc * 2);
            bfh[nf][1] = *(const uint32_t*)(sm + 12288 + n * 48 + (lc + 8) * 2);
            bfl[nf][0] = *(const uint32_t*)(sm + 18432 + n * 48 + lc * 2);
            bfl[nf][1] = *(const uint32_t*)(sm + 18432 + n * 48 + (lc + 8) * 2);
        }
#pragma unroll
        for (int mi = 0; mi < 2; mi++)
#pragma unroll
            for (int nf = 0; nf < 8; nf++) {
                mma_bf16(acc[mi][nf], afh[mi], bfh[nf]);
                mma_bf16(acc[mi][nf], afh[mi], bfl[nf]);
                mma_bf16(acc[mi][nf], afl[mi], bfh[nf]);
            }
        __syncthreads();
    }

#pragma unroll
    for (int mi = 0; mi < 2; mi++)
#pragma unroll
        for (int nf = 0; nf < 8; nf++) {
            int r = m0 + m_off + mi * 16 + lr;
            int c = n0 + n_off + nf * 8 + lc;
            float2 bv = *(const float2*)&bias[c];
            float2 o0 = make_float2(acc[mi][nf][0] + bv.x, acc[mi][nf][1] + bv.y);
            float2 o1 = make_float2(acc[mi][nf][2] + bv.x, acc[mi][nf][3] + bv.y);
            *(float2*)&g_xg[(size_t)r * G4 + c] = o0;
            *(float2*)&g_xg[(size_t)(r + 8) * G4 + c] = o1;
        }
}

// ---------------- zero initial h splits ----------------
__global__ void zero_h() {
    int i = blockIdx.x * 256 + threadIdx.x;
    if (i < BB * HH / 2) {
        ((unsigned*)g_hpA)[i] = 0u;
        ((unsigned*)g_lpA)[i] = 0u;
    }
}

// ==================== persistent mma.sync LSTM ====================
// 128 blocks x 256 thr; block = 32 batch x 64 gate-cols (n = gate*16 + jj).
// Wh bf16 hi/lo resident in SMEM (padded 520-elem rows); h global bf16 ping-pong.
#define L_BHI 0
#define L_BLO 66560
#define L_AHI 133120
#define L_ALO 166400
#define L_GS  199680
#define L_CS  208000
#define L_SMEM 210048

__global__ void __launch_bounds__(256, 1)
lstm_mma(const float* __restrict__ Wh, int layer) {
    extern __shared__ __align__(16) uint8_t sm[];
    const int tid = threadIdx.x, lane = tid & 31, wid = tid >> 5;
    const int b0 = (blockIdx.x >> 5) * 32;
    const int j0 = (blockIdx.x & 31) * 16;
    const int m_off = (wid >> 2) * 16, n_off = (wid & 3) * 16;
    const int lr = lane >> 2, lc = (lane & 3) * 2;

    // Wh slice -> bf16 hi/lo, layout [n][k] with 520-elem padded rows
    for (int i = tid; i < 64 * HH; i += 256) {
        int n = i & 63, k = i >> 6;
        float w = Wh[k * G4 + (n >> 4) * HH + j0 + (n & 15)];
        __nv_bfloat16 h_, l_;
        bsplit(w, &h_, &l_);
        *(__nv_bfloat16*)(sm + L_BHI + ((size_t)n * 520 + k) * 2) = h_;
        *(__nv_bfloat16*)(sm + L_BLO + ((size_t)n * 520 + k) * 2) = l_;
    }
    for (int i = tid; i < 512; i += 256) ((float*)(sm + L_CS))[i] = 0.f;
    __syncthreads();

    float* Gs = (float*)(sm + L_GS);
    float* cs = (float*)(sm + L_CS);
    const int p0 = tid, p1 = tid + 256;
    const int rr0 = p0 >> 4, jj0 = p0 & 15;
    const int rr1 = p1 >> 4, jj1 = p1 & 15;

    for (int t = 0; t < TT; t++) {
        const __nv_bfloat16* hph = (t & 1) ? g_hpB : g_hpA;
        const __nv_bfloat16* hpl = (t & 1) ? g_lpB : g_lpA;

        // prefetch xg for this thread's 2 gate elements
        const float* xb0 = g_xg + ((size_t)(b0 + rr0) * TT + t) * G4 + j0 + jj0;
        const float* xb1 = g_xg + ((size_t)(b0 + rr1) * TT + t) * G4 + j0 + jj1;
        float x00 = xb0[0], x01 = xb0[512], x02 = xb0[1024], x03 = xb0[1536];
        float x10 = xb1[0], x11 = xb1[512], x12 = xb1[1024], x13 = xb1[1536];

        // load h tile (32 x 512 bf16, hi+lo) into padded SMEM
#pragma unroll
        for (int idx = tid; idx < 2048; idx += 256) {
            int row = idx >> 6, k8 = (idx & 63) * 8;
            *(uint4*)(sm + L_AHI + row * 1040 + k8 * 2) =
                *(const uint4*)(hph + (size_t)(b0 + row) * HH + k8);
            *(uint4*)(sm + L_ALO + row * 1040 + k8 * 2) =
                *(const uint4*)(hpl + (size_t)(b0 + row) * HH + k8);
        }
        __syncthreads();

        float acc[2][4] = {{0.f, 0.f, 0.f, 0.f}, {0.f, 0.f, 0.f, 0.f}};
        const int ar0 = m_off + lr;
#pragma unroll 2
        for (int kk = 0; kk < 512; kk += 16) {
            int kb = (kk + lc) * 2;
            uint32_t ah[4], al[4];
            ah[0] = *(const uint32_t*)(sm + L_AHI + ar0 * 1040 + kb);
            ah[1] = *(const uint32_t*)(sm + L_AHI + (ar0 + 8) * 1040 + kb);
            ah[2] = *(const uint32_t*)(sm + L_AHI + ar0 * 1040 + kb + 16);
            ah[3] = *(const uint32_t*)(sm + L_AHI + (ar0 + 8) * 1040 + kb + 16);
            al[0] = *(const uint32_t*)(sm + L_ALO + ar0 * 1040 + kb);
            al[1] = *(const uint32_t*)(sm + L_ALO + (ar0 + 8) * 1040 + kb);
            al[2] = *(const uint32_t*)(sm + L_ALO + ar0 * 1040 + kb + 16);
            al[3] = *(const uint32_t*)(sm + L_ALO + (ar0 + 8) * 1040 + kb + 16);
#pragma unroll
            for (int nf = 0; nf < 2; nf++) {
                int n = n_off + nf * 8 + lr;
                uint32_t bh[2], bl[2];
                bh[0] = *(const uint32_t*)(sm + L_BHI + n * 1040 + kb);
                bh[1] = *(const uint32_t*)(sm + L_BHI + n * 1040 + kb + 16);
                bl[0] = *(const uint32_t*)(sm + L_BLO + n * 1040 + kb);
                bl[1] = *(const uint32_t*)(sm + L_BLO + n * 1040 + kb + 16);
                mma_bf16(acc[nf], ah, bh);
                mma_bf16(acc[nf], ah, bl);
                mma_bf16(acc[nf], al, bh);
            }
        }
#pragma unroll
        for (int nf = 0; nf < 2; nf++) {
            int r = m_off + lr, c = n_off + nf * 8 + lc;
            Gs[r * 65 + c] = acc[nf][0];
            Gs[r * 65 + c + 1] = acc[nf][1];
            Gs[(r + 8) * 65 + c] = acc[nf][2];
            Gs[(r + 8) * 65 + c + 1] = acc[nf][3];
        }
        __syncthreads();

        __nv_bfloat16* hnh = (t & 1) ? g_hpA : g_hpB;
        __nv_bfloat16* hnl = (t & 1) ? g_lpA : g_lpB;
        {
            float iv = Gs[rr0 * 65 + jj0] + x00;
            float fv = Gs[rr0 * 65 + 16 + jj0] + x01;
            float cv = Gs[rr0 * 65 + 32 + jj0] + x02;
            float ov = Gs[rr0 * 65 + 48 + jj0] + x03;
            iv = 1.f / (1.f + __expf(-iv));
            fv = 1.f / (1.f + __expf(-fv));
            ov = 1.f / (1.f + __expf(-ov));
            cv = tanhf(cv);
            float c = fv * cs[p0] + iv * cv;
            cs[p0] = c;
            float h = ov * tanhf(c);
            __nv_bfloat16 vh, vl;
            bsplit(h, &vh, &vl);
            hnh[(size_t)(b0 + rr0) * HH + j0 + jj0] = vh;
            hnl[(size_t)(b0 + rr0) * HH + j0 + jj0] = vl;
            if (layer == 0) {
                g_sh[((size_t)(b0 + rr0) * TT + t) * HH + j0 + jj0] = vh;
                g_sl[((size_t)(b0 + rr0) * TT + t) * HH + j0 + jj0] = vl;
            } else if (t == TT - 1) {
                g_hfin[(size_t)(b0 + rr0) * HH + j0 + jj0] = h;
            }
        }
        {
            float iv = Gs[rr1 * 65 + jj1] + x10;
            float fv = Gs[rr1 * 65 + 16 + jj1] + x11;
            float cv = Gs[rr1 * 65 + 32 + jj1] + x12;
            float ov = Gs[rr1 * 65 + 48 + jj1] + x13;
            iv = 1.f / (1.f + __expf(-iv));
            fv = 1.f / (1.f + __expf(-fv));
            ov = 1.f / (1.f + __expf(-ov));
            cv = tanhf(cv);
            float c = fv * cs[p1] + iv * cv;
            cs[p1] = c;
            float h = ov * tanhf(c);
            __nv_bfloat16 vh, vl;
            bsplit(h, &vh, &vl);
            hnh[(size_t)(b0 + rr1) * HH + j0 + jj1] = vh;
            hnl[(size_t)(b0 + rr1) * HH + j0 + jj1] = vl;
            if (layer == 0) {
                g_sh[((size_t)(b0 + rr1) * TT + t) * HH + j0 + jj1] = vh;
                g_sl[((size_t)(b0 + rr1) * TT + t) * HH + j0 + jj1] = vl;
            } else if (t == TT - 1) {
                g_hfin[(size_t)(b0 + rr1) * HH + j0 + jj1] = h;
            }
        }
        if (t < TT - 1) grid_bar();
    }
}

// ---------------- layernorm (eps=1e-3) on g_hfin ----------------
__global__ void layernorm(const float* __restrict__ gamma, const float* __restrict__ beta) {
    const int b = blockIdx.x, tid = threadIdx.x;
    const float* __restrict__ h = &g_hfin[b * HH];
    __shared__ float red[8];
    __shared__ float bc_mu, bc_rs;
    float s = 0.f;
    for (int j = tid; j < HH; j += 256) s += h[j];
#pragma unroll
    for (int o = 16; o; o >>= 1) s += __shfl_xor_sync(0xffffffffu, s, o);
    if ((tid & 31) == 0) red[tid >> 5] = s;
    __syncthreads();
    if (tid == 0) {
        float ts = 0.f;
        for (int i = 0; i < 8; i++) ts += red[i];
        bc_mu = ts / (float)HH;
    }
    __syncthreads();
    float mu = bc_mu;
    float v = 0.f;
    for (int j = tid; j < HH; j += 256) { float dd = h[j] - mu; v += dd * dd; }
#pragma unroll
    for (int o = 16; o; o >>= 1) v += __shfl_xor_sync(0xffffffffu, v, o);
    __syncthreads();
    if ((tid & 31) == 0) red[tid >> 5] = v;
    __syncthreads();
    if (tid == 0) {
        float ts = 0.f;
        for (int i = 0; i < 8; i++) ts += red[i];
        bc_rs = rsqrtf(ts / (float)HH + 1e-3f);
    }
    __syncthreads();
    float rs = bc_rs;
    for (int j = tid; j < HH; j += 256)
        g_ln[b * HH + j] = (h[j] - mu) * rs * gamma[j] + beta[j];
}

// ---------------- dense2 + relu ----------------
__global__ void dense2(const float* __restrict__ W2, const float* __restrict__ b2) {
    const int b = blockIdx.x, c = threadIdx.x;
    const float* __restrict__ h = &g_ln[b * HH];
    float s = b2[c];
    for (int k = 0; k < HH; k++) s += h[k] * W2[k * 256 + c];
    g_d2[b * 256 + c] = fmaxf(s, 0.f);
}

// ---------------- dense3 ----------------
__global__ void dense3(const float* __restrict__ W3, const float* __restrict__ b3,
                       float* __restrict__ out) {
    const int b = blockIdx.x, tid = threadIdx.x;
    float s = g_d2[b * 256 + tid] * W3[tid];
#pragma unroll
    for (int o = 16; o; o >>= 1) s += __shfl_xor_sync(0xffffffffu, s, o);
    __shared__ float red[8];
    if ((tid & 31) == 0) red[tid >> 5] = s;
    __syncthreads();
    if (tid == 0) {
        float ts = 0.f;
        for (int i = 0; i < 8; i++) ts += red[i];
        out[b] = ts + b3[0];
    }
}

// ---------------- launch ----------------
extern "C" void kernel_launch(void* const* d_in, const int* in_sizes, int n_in,
                              void* d_out, int out_size) {
    const float* x     = (const float*)d_in[0];
    const float* W1    = (const float*)d_in[1];
    const float* b1    = (const float*)d_in[2];
    const float* Wx1   = (const float*)d_in[3];
    const float* Wh1   = (const float*)d_in[4];
    const float* bl1   = (const float*)d_in[5];
    const float* Wx2   = (const float*)d_in[6];
    const float* Wh2   = (const float*)d_in[7];
    const float* bl2   = (const float*)d_in[8];
    const float* gamma = (const float*)d_in[9];
    const float* beta  = (const float*)d_in[10];
    const float* W2    = (const float*)d_in[11];
    const float* b2    = (const float*)d_in[12];
    const float* W3    = (const float*)d_in[13];
    const float* b3    = (const float*)d_in[14];
    float* out = (float*)d_out;

    static int init_done = 0;
    if (!init_done) {
        cudaFuncSetAttribute(lstm_mma, cudaFuncAttributeMaxDynamicSharedMemorySize,
                             L_SMEM);
        init_done = 1;
    }

    dense1_norm<<<(BB * TT) / 16, 256>>>(x, W1, b1);
    convW<<<(HH * G4 + 255) / 256, 256>>>(Wx1, 0);
    convW<<<(HH * G4 + 255) / 256, 256>>>(Wx2, 1);

    gemm_xg<<<dim3(G4 / 128, (BB * TT) / 128), 256>>>(0, bl1);
    zero_h<<<(BB * HH / 2 + 255) / 256, 256>>>();
    lstm_mma<<<NBLK, 256, L_SMEM>>>(Wh1, 0);

    gemm_xg<<<dim3(G4 / 128, (BB * TT) / 128), 256>>>(1, bl2);
    zero_h<<<(BB * HH / 2 + 255) / 256, 256>>>();
    lstm_mma<<<NBLK, 256, L_SMEM>>>(Wh2, 1);

    layernorm<<<BB, 256>>>(gamma, beta);
    dense2<<<BB, 256>>>(W2, b2);
    dense3<<<BB, 256>>>(W3, b3, out);
}

// round 8
// speedup vs baseline: 1.8531x; 1.0145x over previous
#include <cuda_runtime.h>
#include <cuda_bf16.h>
#include <math.h>
#include <stdint.h>

#define BB 128
#define TT 256
#define FF 64
#define HH 512
#define G4 2048
#define NBLK 128  // persistent LSTM grid

// ---------------- mma / ldmatrix / cp.async helpers (arch-generic) ----------
__device__ __forceinline__ void mma_bf16(float* d, const uint32_t* a, const uint32_t* b) {
    asm volatile(
        "mma.sync.aligned.m16n8k16.row.col.f32.bf16.bf16.f32 "
        "{%0,%1,%2,%3}, {%4,%5,%6,%7}, {%8,%9}, {%0,%1,%2,%3};"
        : "+f"(d[0]), "+f"(d[1]), "+f"(d[2]), "+f"(d[3])
        : "r"(a[0]), "r"(a[1]), "r"(a[2]), "r"(a[3]), "r"(b[0]), "r"(b[1]));
}
__device__ __forceinline__ void ldsm4(uint32_t* r, uint32_t addr) {
    asm volatile("ldmatrix.sync.aligned.m8n8.x4.shared.b16 {%0,%1,%2,%3}, [%4];"
        : "=r"(r[0]), "=r"(r[1]), "=r"(r[2]), "=r"(r[3]) : "r"(addr));
}
__device__ __forceinline__ uint32_t smem_u32(const void* p) {
    uint32_t a;
    asm("{ .reg .u64 t; cvta.to.shared.u64 t, %1; cvt.u32.u64 %0, t; }"
        : "=r"(a) : "l"(p));
    return a;
}
__device__ __forceinline__ void cp16(uint32_t dst, const void* src) {
    asm volatile("cp.async.ca.shared.global [%0], [%1], 16;"
        :: "r"(dst), "l"(src) : "memory");
}
#define CP_COMMIT() asm volatile("cp.async.commit_group;" ::: "memory")
#define CP_WAIT0()  asm volatile("cp.async.wait_group 0;" ::: "memory")
#define CP_WAIT1()  asm volatile("cp.async.wait_group 1;" ::: "memory")

__device__ __forceinline__ void bsplit(float w, __nv_bfloat16* hi, __nv_bfloat16* lo) {
    __nv_bfloat16 h = __float2bfloat16(w);
    *hi = h;
    *lo = __float2bfloat16(w - __bfloat162float(h));
}

// ---------------- scratch ----------------
__device__ __nv_bfloat16 g_hh[BB * TT * HH], g_hl[BB * TT * HH];
__device__ __nv_bfloat16 g_sh[BB * TT * HH], g_sl[BB * TT * HH];
__device__ __nv_bfloat16 g_Wxh[2][G4 * HH], g_Wxl[2][G4 * HH];
__device__ float g_xg[(size_t)BB * TT * G4];
__device__ __nv_bfloat16 g_hpA[BB * HH], g_hpB[BB * HH];
__device__ __nv_bfloat16 g_lpA[BB * HH], g_lpB[BB * HH];
__device__ float g_hfin[BB * HH];
__device__ float g_ln[BB * HH];
__device__ float g_d2[BB * (HH / 2)];
__device__ unsigned g_cnt[8];
__device__ unsigned g_scnt = 0;
__device__ unsigned g_gen = 0;

// ---------------- two-level grid barrier (128 blocks, 8 groups of 16) -------
__device__ __forceinline__ void grid_bar() {
    __syncthreads();
    if (threadIdx.x == 0) {
        __threadfence();
        unsigned gen = *(volatile unsigned*)&g_gen;
        if (atomicAdd(&g_cnt[blockIdx.x & 7], 1u) == 15u) {
            g_cnt[blockIdx.x & 7] = 0u;
            __threadfence();
            if (atomicAdd(&g_scnt, 1u) == 7u) {
                g_scnt = 0u;
                __threadfence();
                atomicAdd(&g_gen, 1u);
            } else {
                while (*(volatile unsigned*)&g_gen == gen) {}
            }
        } else {
            while (*(volatile unsigned*)&g_gen == gen) {}
        }
        __threadfence();
    }
    __syncthreads();
}

// ---------------- dense1 + L2-norm scale (writes bf16 splits) ---------------
__global__ void dense1_norm(const float* __restrict__ x, const float* __restrict__ W1,
                            const float* __restrict__ b1) {
    __shared__ float xs[16][FF];
    __shared__ float hs[16][HH];
    const int tid = threadIdx.x;
    const int m0 = blockIdx.x * 16;
    for (int i = tid; i < 16 * FF; i += 256)
        xs[i / FF][i % FF] = x[(m0 + i / FF) * FF + i % FF];
    __syncthreads();
    const int c0 = tid * 2;
    float a0[16], a1[16];
#pragma unroll
    for (int r = 0; r < 16; r++) { a0[r] = 0.f; a1[r] = 0.f; }
    for (int k = 0; k < FF; k++) {
        float w0 = W1[k * HH + c0], w1 = W1[k * HH + c0 + 1];
#pragma unroll
        for (int r = 0; r < 16; r++) { float xv = xs[r][k]; a0[r] += xv * w0; a1[r] += xv * w1; }
    }
    float bb0 = b1[c0], bb1 = b1[c0 + 1];
#pragma unroll
    for (int r = 0; r < 16; r++) { hs[r][c0] = a0[r] + bb0; hs[r][c0 + 1] = a1[r] + bb1; }
    __syncthreads();
    int wid = tid >> 5, lane = tid & 31;
#pragma unroll
    for (int rr = 0; rr < 2; rr++) {
        int r = wid * 2 + rr;
        float ss = 0.f;
        for (int c = lane; c < HH; c += 32) { float v = hs[r][c]; ss += v * v; }
#pragma unroll
        for (int o = 16; o; o >>= 1) ss += __shfl_xor_sync(0xffffffffu, ss, o);
        float sc = sqrtf((float)HH) / fmaxf(sqrtf(ss), 1e-12f);
        for (int c = lane; c < HH; c += 32) {
            float v = hs[r][c] * sc;
            __nv_bfloat16 vh, vl;
            bsplit(v, &vh, &vl);
            g_hh[(size_t)(m0 + r) * HH + c] = vh;
            g_hl[(size_t)(m0 + r) * HH + c] = vl;
        }
    }
}

// ---------------- Wx -> transposed bf16 splits [n][k] ----------------
__global__ void convW(const float* __restrict__ W, int layer) {
    int i = blockIdx.x * 256 + threadIdx.x;
    if (i < HH * G4) {
        int k = i / G4, n = i % G4;
        __nv_bfloat16 h_, l_;
        bsplit(W[i], &h_, &l_);
        g_Wxh[layer][(size_t)n * HH + k] = h_;
        g_Wxl[layer][(size_t)n * HH + k] = l_;
    }
}

// ---------------- xg GEMM: cp.async 2-stage + ldmatrix + bf16-split mma -----
// block 128(M)x128(N), 8 warps as 4(M)x2(N), warp 32x64
#define XS_STAGE 24576   // 4 arrays * 128 rows * 48B
#define XS_SMEM  (2 * XS_STAGE)

__global__ void __launch_bounds__(256) gemm_xg(int layer, const float* __restrict__ bias) {
    const __nv_bfloat16* __restrict__ Ah = layer ? g_sh : g_hh;
    const __nv_bfloat16* __restrict__ Al = layer ? g_sl : g_hl;
    const __nv_bfloat16* __restrict__ Bh = g_Wxh[layer];
    const __nv_bfloat16* __restrict__ Bl = g_Wxl[layer];

    extern __shared__ __align__(16) uint8_t smd[];
    const int tid = threadIdx.x;
    const int lane = tid & 31, wid = tid >> 5;
    const int n0 = blockIdx.x * 128, m0 = blockIdx.y * 128;
    const int m_off = (wid >> 1) * 32, n_off = (wid & 1) * 64;
    const int lr = lane >> 2, lc = (lane & 3) * 2;

    float acc[2][8][4];
#pragma unroll
    for (int i = 0; i < 2; i++)
#pragma unroll
        for (int j = 0; j < 8; j++)
#pragma unroll
            for (int q = 0; q < 4; q++) acc[i][j][q] = 0.f;

    const int row = tid >> 1, half = tid & 1;
    const __nv_bfloat16* pAh = Ah + (size_t)(m0 + row) * HH + half * 8;
    const __nv_bfloat16* pAl = Al + (size_t)(m0 + row) * HH + half * 8;
    const __nv_bfloat16* pBh = Bh + (size_t)(n0 + row) * HH + half * 8;
    const __nv_bfloat16* pBl = Bl + (size_t)(n0 + row) * HH + half * 8;
    const uint32_t smb = smem_u32(smd);
    const uint32_t sdst = smb + row * 48 + half * 16;

    // prologue: stage 0
    cp16(sdst, pAh);
    cp16(sdst + 6144, pAl);
    cp16(sdst + 12288, pBh);
    cp16(sdst + 18432, pBl);
    CP_COMMIT();

    int s = 0;
    for (int kc = 0; kc < HH; kc += 16) {
        if (kc + 16 < HH) {
            uint32_t d2 = sdst + (s ^ 1) * XS_STAGE;
            cp16(d2, pAh + kc + 16);
            cp16(d2 + 6144, pAl + kc + 16);
            cp16(d2 + 12288, pBh + kc + 16);
            cp16(d2 + 18432, pBl + kc + 16);
            CP_COMMIT();
            CP_WAIT1();
        } else {
            CP_WAIT0();
        }
        __syncthreads();
        const uint32_t sb = smb + s * XS_STAGE;

        uint32_t afh[2][4], afl[2][4];
#pragma unroll
        for (int mi = 0; mi < 2; mi++) {
            uint32_t ar = sb + (m_off + mi * 16 + (lane & 15)) * 48 + (lane >> 4) * 16;
            ldsm4(afh[mi], ar);
            ldsm4(afl[mi], ar + 6144);
        }
        uint32_t bfh[8][2], bfl[8][2];
#pragma unroll
        for (int g = 0; g < 4; g++) {
            uint32_t br = sb + 12288 + (n_off + g * 16 + (lane & 15)) * 48 + (lane >> 4) * 16;
            uint32_t tt[4];
            ldsm4(tt, br);
            bfh[2 * g][0] = tt[0]; bfh[2 * g + 1][0] = tt[1];
            bfh[2 * g][1] = tt[2]; bfh[2 * g + 1][1] = tt[3];
            ldsm4(tt, br + 6144);
            bfl[2 * g][0] = tt[0]; bfl[2 * g + 1][0] = tt[1];
            bfl[2 * g][1] = tt[2]; bfl[2 * g + 1][1] = tt[3];
        }
#pragma unroll
        for (int mi = 0; mi < 2; mi++)
#pragma unroll
            for (int nf = 0; nf < 8; nf++) {
                mma_bf16(acc[mi][nf], afh[mi], bfh[nf]);
                mma_bf16(acc[mi][nf], afh[mi], bfl[nf]);
                mma_bf16(acc[mi][nf], afl[mi], bfh[nf]);
            }
        __syncthreads();
        s ^= 1;
    }

#pragma unroll
    for (int mi = 0; mi < 2; mi++)
#pragma unroll
        for (int nf = 0; nf < 8; nf++) {
            int r = m0 + m_off + mi * 16 + lr;
            int c = n0 + n_off + nf * 8 + lc;
            float2 bv = *(const float2*)&bias[c];
            *(float2*)&g_xg[(size_t)r * G4 + c] =
                make_float2(acc[mi][nf][0] + bv.x, acc[mi][nf][1] + bv.y);
            *(float2*)&g_xg[(size_t)(r + 8) * G4 + c] =
                make_float2(acc[mi][nf][2] + bv.x, acc[mi][nf][3] + bv.y);
        }
}

// ---------------- zero initial h splits ----------------
__global__ void zero_h() {
    int i = blockIdx.x * 256 + threadIdx.x;
    if (i < BB * HH / 2) {
        ((unsigned*)g_hpA)[i] = 0u;
        ((unsigned*)g_lpA)[i] = 0u;
    }
}

// ==================== persistent mma.sync LSTM ====================
// 128 blocks x 256 thr; block = 32 batch x 64 gate-cols (n = gate*16 + jj).
#define L_BHI 0
#define L_BLO 66560
#define L_AHI 133120
#define L_ALO 166400
#define L_GS  199680
#define L_CS  208000
#define L_SMEM 210048

__global__ void __launch_bounds__(256, 1)
lstm_mma(const float* __restrict__ Wh, int layer) {
    extern __shared__ __align__(16) uint8_t sm[];
    const int tid = threadIdx.x, lane = tid & 31, wid = tid >> 5;
    const int b0 = (blockIdx.x >> 5) * 32;
    const int j0 = (blockIdx.x & 31) * 16;
    const int m_off = (wid >> 2) * 16, n_off = (wid & 3) * 16;
    const int lr = lane >> 2, lc = (lane & 3) * 2;

    // Wh slice -> bf16 hi/lo, [n][k] padded rows (520 elems = 1040B)
    for (int i = tid; i < 64 * HH; i += 256) {
        int n = i & 63, k = i >> 6;
        float w = Wh[k * G4 + (n >> 4) * HH + j0 + (n & 15)];
        __nv_bfloat16 h_, l_;
        bsplit(w, &h_, &l_);
        *(__nv_bfloat16*)(sm + L_BHI + ((size_t)n * 520 + k) * 2) = h_;
        *(__nv_bfloat16*)(sm + L_BLO + ((size_t)n * 520 + k) * 2) = l_;
    }
    for (int i = tid; i < 512; i += 256) ((float*)(sm + L_CS))[i] = 0.f;
    __syncthreads();

    float* Gs = (float*)(sm + L_GS);
    float* cs = (float*)(sm + L_CS);
    const uint32_t smb = smem_u32(sm);
    const int p0 = tid, p1 = tid + 256;
    const int rr0 = p0 >> 4, jj0 = p0 & 15;
    const int rr1 = p1 >> 4, jj1 = p1 & 15;

    // per-warp ldmatrix row addresses (k-offset added per chunk)
    const uint32_t rAh = smb + L_AHI + (m_off + (lane & 15)) * 1040 + (lane >> 4) * 16;
    const uint32_t rAl = smb + L_ALO + (m_off + (lane & 15)) * 1040 + (lane >> 4) * 16;
    const uint32_t rBh = smb + L_BHI + (n_off + (lane & 15)) * 1040 + (lane >> 4) * 16;
    const uint32_t rBl = smb + L_BLO + (n_off + (lane & 15)) * 1040 + (lane >> 4) * 16;

    for (int t = 0; t < TT; t++) {
        const __nv_bfloat16* hph = (t & 1) ? g_hpB : g_hpA;
        const __nv_bfloat16* hpl = (t & 1) ? g_lpB : g_lpA;

        // prefetch xg (long-latency LDG, overlaps with tile load)
        const float* xb0 = g_xg + ((size_t)(b0 + rr0) * TT + t) * G4 + j0 + jj0;
        const float* xb1 = g_xg + ((size_t)(b0 + rr1) * TT + t) * G4 + j0 + jj1;
        float x00 = xb0[0], x01 = xb0[512], x02 = xb0[1024], x03 = xb0[1536];
        float x10 = xb1[0], x11 = xb1[512], x12 = xb1[1024], x13 = xb1[1536];

        // h tile (32 x 512 bf16, hi+lo) via cp.async
#pragma unroll
        for (int idx = tid; idx < 2048; idx += 256) {
            int row = idx >> 6, k8 = (idx & 63) * 8;
            cp16(smb + L_AHI + row * 1040 + k8 * 2, hph + (size_t)(b0 + row) * HH + k8);
            cp16(smb + L_ALO + row * 1040 + k8 * 2, hpl + (size_t)(b0 + row) * HH + k8);
        }
        CP_COMMIT();
        CP_WAIT0();
        __syncthreads();

        float acc[2][4] = {{0.f, 0.f, 0.f, 0.f}, {0.f, 0.f, 0.f, 0.f}};
#pragma unroll 2
        for (int kk = 0; kk < 512; kk += 16) {
            uint32_t ah[4], al[4], tb[4];
            uint32_t bh0[2], bh1[2], bl0[2], bl1[2];
            ldsm4(ah, rAh + kk * 2);
            ldsm4(al, rAl + kk * 2);
            ldsm4(tb, rBh + kk * 2);
            bh0[0] = tb[0]; bh1[0] = tb[1]; bh0[1] = tb[2]; bh1[1] = tb[3];
            ldsm4(tb, rBl + kk * 2);
            bl0[0] = tb[0]; bl1[0] = tb[1]; bl0[1] = tb[2]; bl1[1] = tb[3];
            mma_bf16(acc[0], ah, bh0);
            mma_bf16(acc[0], ah, bl0);
            mma_bf16(acc[0], al, bh0);
            mma_bf16(acc[1], ah, bh1);
            mma_bf16(acc[1], ah, bl1);
            mma_bf16(acc[1], al, bh1);
        }
#pragma unroll
        for (int nf = 0; nf < 2; nf++) {
            int r = m_off + lr, c = n_off + nf * 8 + lc;
            Gs[r * 65 + c] = acc[nf][0];
            Gs[r * 65 + c + 1] = acc[nf][1];
            Gs[(r + 8) * 65 + c] = acc[nf][2];
            Gs[(r + 8) * 65 + c + 1] = acc[nf][3];
        }
        __syncthreads();

        __nv_bfloat16* hnh = (t & 1) ? g_hpA : g_hpB;
        __nv_bfloat16* hnl = (t & 1) ? g_lpA : g_lpB;
        {
            float iv = Gs[rr0 * 65 + jj0] + x00;
            float fv = Gs[rr0 * 65 + 16 + jj0] + x01;
            float cv = Gs[rr0 * 65 + 32 + jj0] + x02;
            float ov = Gs[rr0 * 65 + 48 + jj0] + x03;
            iv = 1.f / (1.f + __expf(-iv));
            fv = 1.f / (1.f + __expf(-fv));
            ov = 1.f / (1.f + __expf(-ov));
            cv = tanhf(cv);
            float c = fv * cs[p0] + iv * cv;
            cs[p0] = c;
            float h = ov * tanhf(c);
            __nv_bfloat16 vh, vl;
            bsplit(h, &vh, &vl);
            hnh[(size_t)(b0 + rr0) * HH + j0 + jj0] = vh;
            hnl[(size_t)(b0 + rr0) * HH + j0 + jj0] = vl;
            if (layer == 0) {
                g_sh[((size_t)(b0 + rr0) * TT + t) * HH + j0 + jj0] = vh;
                g_sl[((size_t)(b0 + rr0) * TT + t) * HH + j0 + jj0] = vl;
            } else if (t == TT - 1) {
                g_hfin[(size_t)(b0 + rr0) * HH + j0 + jj0] = h;
            }
        }
        {
            float iv = Gs[rr1 * 65 + jj1] + x10;
            float fv = Gs[rr1 * 65 + 16 + jj1] + x11;
            float cv = Gs[rr1 * 65 + 32 + jj1] + x12;
            float ov = Gs[rr1 * 65 + 48 + jj1] + x13;
            iv = 1.f / (1.f + __expf(-iv));
            fv = 1.f / (1.f + __expf(-fv));
            ov = 1.f / (1.f + __expf(-ov));
            cv = tanhf(cv);
            float c = fv * cs[p1] + iv * cv;
            cs[p1] = c;
            float h = ov * tanhf(c);
            __nv_bfloat16 vh, vl;
            bsplit(h, &vh, &vl);
            hnh[(size_t)(b0 + rr1) * HH + j0 + jj1] = vh;
            hnl[(size_t)(b0 + rr1) * HH + j0 + jj1] = vl;
            if (layer == 0) {
                g_sh[((size_t)(b0 + rr1) * TT + t) * HH + j0 + jj1] = vh;
                g_sl[((size_t)(b0 + rr1) * TT + t) * HH + j0 + jj1] = vl;
            } else if (t == TT - 1) {
                g_hfin[(size_t)(b0 + rr1) * HH + j0 + jj1] = h;
            }
        }
        if (t < TT - 1) grid_bar();
    }
}

// ---------------- layernorm (eps=1e-3) on g_hfin ----------------
__global__ void layernorm(const float* __restrict__ gamma, const float* __restrict__ beta) {
    const int b = blockIdx.x, tid = threadIdx.x;
    const float* __restrict__ h = &g_hfin[b * HH];
    __shared__ float red[8];
    __shared__ float bc_mu, bc_rs;
    float s = 0.f;
    for (int j = tid; j < HH; j += 256) s += h[j];
#pragma unroll
    for (int o = 16; o; o >>= 1) s += __shfl_xor_sync(0xffffffffu, s, o);
    if ((tid & 31) == 0) red[tid >> 5] = s;
    __syncthreads();
    if (tid == 0) {
        float ts = 0.f;
        for (int i = 0; i < 8; i++) ts += red[i];
        bc_mu = ts / (float)HH;
    }
    __syncthreads();
    float mu = bc_mu;
    float v = 0.f;
    for (int j = tid; j < HH; j += 256) { float dd = h[j] - mu; v += dd * dd; }
#pragma unroll
    for (int o = 16; o; o >>= 1) v += __shfl_xor_sync(0xffffffffu, v, o);
    __syncthreads();
    if ((tid & 31) == 0) red[tid >> 5] = v;
    __syncthreads();
    if (tid == 0) {
        float ts = 0.f;
        for (int i = 0; i < 8; i++) ts += red[i];
        bc_rs = rsqrtf(ts / (float)HH + 1e-3f);
    }
    __syncthreads();
    float rs = bc_rs;
    for (int j = tid; j < HH; j += 256)
        g_ln[b * HH + j] = (h[j] - mu) * rs * gamma[j] + beta[j];
}

// ---------------- dense2 + relu ----------------
__global__ void dense2(const float* __restrict__ W2, const float* __restrict__ b2) {
    const int b = blockIdx.x, c = threadIdx.x;
    const float* __restrict__ h = &g_ln[b * HH];
    float s = b2[c];
    for (int k = 0; k < HH; k++) s += h[k] * W2[k * 256 + c];
    g_d2[b * 256 + c] = fmaxf(s, 0.f);
}

// ---------------- dense3 ----------------
__global__ void dense3(const float* __restrict__ W3, const float* __restrict__ b3,
                       float* __restrict__ out) {
    const int b = blockIdx.x, tid = threadIdx.x;
    float s = g_d2[b * 256 + tid] * W3[tid];
#pragma unroll
    for (int o = 16; o; o >>= 1) s += __shfl_xor_sync(0xffffffffu, s, o);
    __shared__ float red[8];
    if ((tid & 31) == 0) red[tid >> 5] = s;
    __syncthreads();
    if (tid == 0) {
        float ts = 0.f;
        for (int i = 0; i < 8; i++) ts += red[i];
        out[b] = ts + b3[0];
    }
}

// ---------------- launch ----------------
extern "C" void kernel_launch(void* const* d_in, const int* in_sizes, int n_in,
                              void* d_out, int out_size) {
    const float* x     = (const float*)d_in[0];
    const float* W1    = (const float*)d_in[1];
    const float* b1    = (const float*)d_in[2];
    const float* Wx1   = (const float*)d_in[3];
    const float* Wh1   = (const float*)d_in[4];
    const float* bl1   = (const float*)d_in[5];
    const float* Wx2   = (const float*)d_in[6];
    const float* Wh2   = (const float*)d_in[7];
    const float* bl2   = (const float*)d_in[8];
    const float* gamma = (const float*)d_in[9];
    const float* beta  = (const float*)d_in[10];
    const float* W2    = (const float*)d_in[11];
    const float* b2    = (const float*)d_in[12];
    const float* W3    = (const float*)d_in[13];
    const float* b3    = (const float*)d_in[14];
    float* out = (float*)d_out;

    static int init_done = 0;
    if (!init_done) {
        cudaFuncSetAttribute(lstm_mma, cudaFuncAttributeMaxDynamicSharedMemorySize,
                             L_SMEM);
        cudaFuncSetAttribute(gemm_xg, cudaFuncAttributeMaxDynamicSharedMemorySize,
                             XS_SMEM);
        init_done = 1;
    }

    dense1_norm<<<(BB * TT) / 16, 256>>>(x, W1, b1);
    convW<<<(HH * G4 + 255) / 256, 256>>>(Wx1, 0);
    convW<<<(HH * G4 + 255) / 256, 256>>>(Wx2, 1);

    gemm_xg<<<dim3(G4 / 128, (BB * TT) / 128), 256, XS_SMEM>>>(0, bl1);
    zero_h<<<(BB * HH / 2 + 255) / 256, 256>>>();
    lstm_mma<<<NBLK, 256, L_SMEM>>>(Wh1, 0);

    gemm_xg<<<dim3(G4 / 128, (BB * TT) / 128), 256, XS_SMEM>>>(1, bl2);
    zero_h<<<(BB * HH / 2 + 255) / 256, 256>>>();
    lstm_mma<<<NBLK, 256, L_SMEM>>>(Wh2, 1);

    layernorm<<<BB, 256>>>(gamma, beta);
    dense2<<<BB, 256>>>(W2, b2);
    dense3<<<BB, 256>>>(W3, b3, out);
}

// round 9
// speedup vs baseline: 2.0576x; 1.1104x over previous
#include <cuda_runtime.h>
#include <cuda_bf16.h>
#include <math.h>
#include <stdint.h>

#define BB 128
#define TT 256
#define FF 64
#define HH 512
#define G4 2048
#define NBLK 128  // persistent LSTM grid

// ---------------- mma / ldmatrix / cp.async helpers (arch-generic) ----------
__device__ __forceinline__ void mma_bf16(float* d, const uint32_t* a, const uint32_t* b) {
    asm volatile(
        "mma.sync.aligned.m16n8k16.row.col.f32.bf16.bf16.f32 "
        "{%0,%1,%2,%3}, {%4,%5,%6,%7}, {%8,%9}, {%0,%1,%2,%3};"
        : "+f"(d[0]), "+f"(d[1]), "+f"(d[2]), "+f"(d[3])
        : "r"(a[0]), "r"(a[1]), "r"(a[2]), "r"(a[3]), "r"(b[0]), "r"(b[1]));
}
__device__ __forceinline__ void ldsm4(uint32_t* r, uint32_t addr) {
    asm volatile("ldmatrix.sync.aligned.m8n8.x4.shared.b16 {%0,%1,%2,%3}, [%4];"
        : "=r"(r[0]), "=r"(r[1]), "=r"(r[2]), "=r"(r[3]) : "r"(addr));
}
__device__ __forceinline__ uint32_t smem_u32(const void* p) {
    uint32_t a;
    asm("{ .reg .u64 t; cvta.to.shared.u64 t, %1; cvt.u32.u64 %0, t; }"
        : "=r"(a) : "l"(p));
    return a;
}
__device__ __forceinline__ void cp16(uint32_t dst, const void* src) {
    asm volatile("cp.async.ca.shared.global [%0], [%1], 16;"
        :: "r"(dst), "l"(src) : "memory");
}
#define CP_COMMIT() asm volatile("cp.async.commit_group;" ::: "memory")
#define CP_WAIT0()  asm volatile("cp.async.wait_group 0;" ::: "memory")
#define CP_WAIT1()  asm volatile("cp.async.wait_group 1;" ::: "memory")

__device__ __forceinline__ void bsplit(float w, __nv_bfloat16* hi, __nv_bfloat16* lo) {
    __nv_bfloat16 h = __float2bfloat16(w);
    *hi = h;
    *lo = __float2bfloat16(w - __bfloat162float(h));
}

// ---------------- scratch ----------------
__device__ __nv_bfloat16 g_hh[BB * TT * HH], g_hl[BB * TT * HH];
__device__ __nv_bfloat16 g_sh[BB * TT * HH], g_sl[BB * TT * HH];
__device__ __nv_bfloat16 g_Wxh[2][G4 * HH], g_Wxl[2][G4 * HH];
__device__ float g_xg[(size_t)BB * TT * G4];
__device__ __nv_bfloat16 g_hpA[BB * HH], g_hpB[BB * HH];
__device__ __nv_bfloat16 g_lpA[BB * HH], g_lpB[BB * HH];
__device__ float g_hfin[BB * HH];
__device__ float g_ln[BB * HH];
__device__ float g_d2[BB * (HH / 2)];
__device__ unsigned g_cnt4[4];
__device__ unsigned g_gen4[4];

// ------- per-batch-group grid barrier (4 independent groups of 32 blocks) ---
__device__ __forceinline__ void grid_bar4(int grp) {
    __syncthreads();
    if (threadIdx.x == 0) {
        __threadfence();
        unsigned gen = *(volatile unsigned*)&g_gen4[grp];
        if (atomicAdd(&g_cnt4[grp], 1u) == 31u) {
            g_cnt4[grp] = 0u;
            __threadfence();
            atomicAdd(&g_gen4[grp], 1u);
        } else {
            while (*(volatile unsigned*)&g_gen4[grp] == gen) {}
        }
        __threadfence();
    }
    __syncthreads();
}

// ---------------- dense1 + L2-norm scale (writes bf16 splits) ---------------
__global__ void dense1_norm(const float* __restrict__ x, const float* __restrict__ W1,
                            const float* __restrict__ b1) {
    __shared__ float xs[16][FF];
    __shared__ float hs[16][HH];
    const int tid = threadIdx.x;
    const int m0 = blockIdx.x * 16;
    for (int i = tid; i < 16 * FF; i += 256)
        xs[i / FF][i % FF] = x[(m0 + i / FF) * FF + i % FF];
    __syncthreads();
    const int c0 = tid * 2;
    float a0[16], a1[16];
#pragma unroll
    for (int r = 0; r < 16; r++) { a0[r] = 0.f; a1[r] = 0.f; }
    for (int k = 0; k < FF; k++) {
        float w0 = W1[k * HH + c0], w1 = W1[k * HH + c0 + 1];
#pragma unroll
        for (int r = 0; r < 16; r++) { float xv = xs[r][k]; a0[r] += xv * w0; a1[r] += xv * w1; }
    }
    float bb0 = b1[c0], bb1 = b1[c0 + 1];
#pragma unroll
    for (int r = 0; r < 16; r++) { hs[r][c0] = a0[r] + bb0; hs[r][c0 + 1] = a1[r] + bb1; }
    __syncthreads();
    int wid = tid >> 5, lane = tid & 31;
#pragma unroll
    for (int rr = 0; rr < 2; rr++) {
        int r = wid * 2 + rr;
        float ss = 0.f;
        for (int c = lane; c < HH; c += 32) { float v = hs[r][c]; ss += v * v; }
#pragma unroll
        for (int o = 16; o; o >>= 1) ss += __shfl_xor_sync(0xffffffffu, ss, o);
        float sc = sqrtf((float)HH) / fmaxf(sqrtf(ss), 1e-12f);
        for (int c = lane; c < HH; c += 32) {
            float v = hs[r][c] * sc;
            __nv_bfloat16 vh, vl;
            bsplit(v, &vh, &vl);
            g_hh[(size_t)(m0 + r) * HH + c] = vh;
            g_hl[(size_t)(m0 + r) * HH + c] = vl;
        }
    }
}

// ---------------- Wx -> transposed bf16 splits [n][k] ----------------
__global__ void convW(const float* __restrict__ W, int layer) {
    int i = blockIdx.x * 256 + threadIdx.x;
    if (i < HH * G4) {
        int k = i / G4, n = i % G4;
        __nv_bfloat16 h_, l_;
        bsplit(W[i], &h_, &l_);
        g_Wxh[layer][(size_t)n * HH + k] = h_;
        g_Wxl[layer][(size_t)n * HH + k] = l_;
    }
}

// ---------------- xg GEMM: 512 thr, 16 warps (4x4), warp 32x32 --------------
#define XS_STAGE 24576   // 4 arrays * 128 rows * 48B
#define XS_SMEM  (2 * XS_STAGE)

__global__ void __launch_bounds__(512) gemm_xg(int layer, const float* __restrict__ bias) {
    const __nv_bfloat16* __restrict__ Ah = layer ? g_sh : g_hh;
    const __nv_bfloat16* __restrict__ Al = layer ? g_sl : g_hl;
    const __nv_bfloat16* __restrict__ Bh = g_Wxh[layer];
    const __nv_bfloat16* __restrict__ Bl = g_Wxl[layer];

    extern __shared__ __align__(16) uint8_t smd[];
    const int tid = threadIdx.x;
    const int lane = tid & 31, wid = tid >> 5;
    const int n0 = blockIdx.x * 128, m0 = blockIdx.y * 128;
    const int m_off = (wid >> 2) * 32, n_off = (wid & 3) * 32;
    const int lr = lane >> 2, lc = (lane & 3) * 2;

    float acc[2][4][4];
#pragma unroll
    for (int i = 0; i < 2; i++)
#pragma unroll
        for (int j = 0; j < 4; j++)
#pragma unroll
            for (int q = 0; q < 4; q++) acc[i][j][q] = 0.f;

    // copy mapping: 1024 cp16 per stage; each thread 2
    const uint32_t smb = smem_u32(smd);
    int id0 = tid, id1 = tid + 512;
    int arr0 = id0 >> 8, row0 = (id0 >> 1) & 127, hf0 = id0 & 1;
    int arr1 = id1 >> 8, row1 = (id1 >> 1) & 127, hf1 = id1 & 1;
    const __nv_bfloat16* src0 =
        (arr0 == 0 ? Ah + (size_t)(m0 + row0) * HH :
         arr0 == 1 ? Al + (size_t)(m0 + row0) * HH :
         arr0 == 2 ? Bh + (size_t)(n0 + row0) * HH :
                     Bl + (size_t)(n0 + row0) * HH) + hf0 * 8;
    const __nv_bfloat16* src1 =
        (arr1 == 0 ? Ah + (size_t)(m0 + row1) * HH :
         arr1 == 1 ? Al + (size_t)(m0 + row1) * HH :
         arr1 == 2 ? Bh + (size_t)(n0 + row1) * HH :
                     Bl + (size_t)(n0 + row1) * HH) + hf1 * 8;
    const uint32_t dst0 = smb + arr0 * 6144 + row0 * 48 + hf0 * 16;
    const uint32_t dst1 = smb + arr1 * 6144 + row1 * 48 + hf1 * 16;

    cp16(dst0, src0);
    cp16(dst1, src1);
    CP_COMMIT();

    int s = 0;
    for (int kc = 0; kc < HH; kc += 16) {
        if (kc + 16 < HH) {
            cp16(dst0 + (s ^ 1) * XS_STAGE, src0 + kc + 16);
            cp16(dst1 + (s ^ 1) * XS_STAGE, src1 + kc + 16);
            CP_COMMIT();
            CP_WAIT1();
        } else {
            CP_WAIT0();
        }
        __syncthreads();
        const uint32_t sb = smb + s * XS_STAGE;

        uint32_t afh[2][4], afl[2][4];
#pragma unroll
        for (int mi = 0; mi < 2; mi++) {
            uint32_t ar = sb + (m_off + mi * 16 + (lane & 15)) * 48 + (lane >> 4) * 16;
            ldsm4(afh[mi], ar);
            ldsm4(afl[mi], ar + 6144);
        }
        uint32_t bfh[4][2], bfl[4][2];
#pragma unroll
        for (int g = 0; g < 2; g++) {
            uint32_t br = sb + 12288 + (n_off + g * 16 + (lane & 15)) * 48 + (lane >> 4) * 16;
            uint32_t tt[4];
            ldsm4(tt, br);
            bfh[2 * g][0] = tt[0]; bfh[2 * g + 1][0] = tt[1];
            bfh[2 * g][1] = tt[2]; bfh[2 * g + 1][1] = tt[3];
            ldsm4(tt, br + 6144);
            bfl[2 * g][0] = tt[0]; bfl[2 * g + 1][0] = tt[1];
            bfl[2 * g][1] = tt[2]; bfl[2 * g + 1][1] = tt[3];
        }
#pragma unroll
        for (int mi = 0; mi < 2; mi++)
#pragma unroll
            for (int nf = 0; nf < 4; nf++) {
                mma_bf16(acc[mi][nf], afh[mi], bfh[nf]);
                mma_bf16(acc[mi][nf], afh[mi], bfl[nf]);
                mma_bf16(acc[mi][nf], afl[mi], bfh[nf]);
            }
        __syncthreads();
        s ^= 1;
    }

#pragma unroll
    for (int mi = 0; mi < 2; mi++)
#pragma unroll
        for (int nf = 0; nf < 4; nf++) {
            int r = m0 + m_off + mi * 16 + lr;
            int c = n0 + n_off + nf * 8 + lc;
            float2 bv = *(const float2*)&bias[c];
            *(float2*)&g_xg[(size_t)r * G4 + c] =
                make_float2(acc[mi][nf][0] + bv.x, acc[mi][nf][1] + bv.y);
            *(float2*)&g_xg[(size_t)(r + 8) * G4 + c] =
                make_float2(acc[mi][nf][2] + bv.x, acc[mi][nf][3] + bv.y);
        }
}

// ---------------- zero initial h splits ----------------
__global__ void zero_h() {
    int i = blockIdx.x * 256 + threadIdx.x;
    if (i < BB * HH / 2) {
        ((unsigned*)g_hpA)[i] = 0u;
        ((unsigned*)g_lpA)[i] = 0u;
    }
}

// ==================== persistent mma.sync LSTM (512 thr, K-split) ===========
// 128 blocks; block = 32 batch x 64 gate-cols. Warps 0-7: K[0,256), 8-15: K[256,512).
#define L_BHI 0
#define L_BLO 66560
#define L_AHI 133120
#define L_ALO 166400
#define L_GS  199680
#define L_SMEM 216320

__global__ void __launch_bounds__(512, 1)
lstm_mma(const float* __restrict__ Wh, int layer) {
    extern __shared__ __align__(16) uint8_t sm[];
    const int tid = threadIdx.x, lane = tid & 31, wid = tid >> 5;
    const int grp = blockIdx.x >> 5;
    const int b0 = grp * 32;
    const int j0 = (blockIdx.x & 31) * 16;
    const int kh = wid >> 3;                 // K half
    const int wq = wid & 7;
    const int m_off = (wq >> 2) * 16, n_off = (wq & 3) * 16;
    const int lr = lane >> 2, lc = (lane & 3) * 2;

    // Wh slice -> bf16 hi/lo, [n][k] padded rows (520 elems = 1040B)
    for (int i = tid; i < 64 * HH; i += 512) {
        int n = i & 63, k = i >> 6;
        float w = Wh[k * G4 + (n >> 4) * HH + j0 + (n & 15)];
        __nv_bfloat16 h_, l_;
        bsplit(w, &h_, &l_);
        *(__nv_bfloat16*)(sm + L_BHI + ((size_t)n * 520 + k) * 2) = h_;
        *(__nv_bfloat16*)(sm + L_BLO + ((size_t)n * 520 + k) * 2) = l_;
    }
    __syncthreads();

    float* Gs = (float*)(sm + L_GS);         // [2][32][65]
    const uint32_t smb = smem_u32(sm);
    const int rr = tid >> 4, jj = tid & 15;  // gate-math element (1/thread)
    float creg = 0.f;

    const uint32_t rAh = smb + L_AHI + (m_off + (lane & 15)) * 1040 + (lane >> 4) * 16 + kh * 512;
    const uint32_t rAl = smb + L_ALO + (m_off + (lane & 15)) * 1040 + (lane >> 4) * 16 + kh * 512;
    const uint32_t rBh = smb + L_BHI + (n_off + (lane & 15)) * 1040 + (lane >> 4) * 16 + kh * 512;
    const uint32_t rBl = smb + L_BLO + (n_off + (lane & 15)) * 1040 + (lane >> 4) * 16 + kh * 512;

    for (int t = 0; t < TT; t++) {
        const __nv_bfloat16* hph = (t & 1) ? g_hpB : g_hpA;
        const __nv_bfloat16* hpl = (t & 1) ? g_lpB : g_lpA;

        // xg prefetch (1 element's 4 gates per thread)
        const float* xb = g_xg + ((size_t)(b0 + rr) * TT + t) * G4 + j0 + jj;
        float x0 = xb[0], x1 = xb[512], x2 = xb[1024], x3 = xb[1536];

        // h tile (32 x 512 bf16, hi+lo) via cp.async, 4 per thread
#pragma unroll
        for (int idx = tid; idx < 2048; idx += 512) {
            int row = idx >> 6, k8 = (idx & 63) * 8;
            cp16(smb + L_AHI + row * 1040 + k8 * 2, hph + (size_t)(b0 + row) * HH + k8);
            cp16(smb + L_ALO + row * 1040 + k8 * 2, hpl + (size_t)(b0 + row) * HH + k8);
        }
        CP_COMMIT();
        CP_WAIT0();
        __syncthreads();

        float acc[2][4] = {{0.f, 0.f, 0.f, 0.f}, {0.f, 0.f, 0.f, 0.f}};
#pragma unroll 2
        for (int kk = 0; kk < 256; kk += 16) {
            uint32_t ah[4], al[4], tb[4];
            uint32_t bh0[2], bh1[2], bl0[2], bl1[2];
            ldsm4(ah, rAh + kk * 2);
            ldsm4(al, rAl + kk * 2);
            ldsm4(tb, rBh + kk * 2);
            bh0[0] = tb[0]; bh1[0] = tb[1]; bh0[1] = tb[2]; bh1[1] = tb[3];
            ldsm4(tb, rBl + kk * 2);
            bl0[0] = tb[0]; bl1[0] = tb[1]; bl0[1] = tb[2]; bl1[1] = tb[3];
            mma_bf16(acc[0], ah, bh0);
            mma_bf16(acc[0], ah, bl0);
            mma_bf16(acc[0], al, bh0);
            mma_bf16(acc[1], ah, bh1);
            mma_bf16(acc[1], ah, bl1);
            mma_bf16(acc[1], al, bh1);
        }
        {
            float* Gk = Gs + kh * (32 * 65);
#pragma unroll
            for (int nf = 0; nf < 2; nf++) {
                int r = m_off + lr, c = n_off + nf * 8 + lc;
                Gk[r * 65 + c] = acc[nf][0];
                Gk[r * 65 + c + 1] = acc[nf][1];
                Gk[(r + 8) * 65 + c] = acc[nf][2];
                Gk[(r + 8) * 65 + c + 1] = acc[nf][3];
            }
        }
        __syncthreads();

        __nv_bfloat16* hnh = (t & 1) ? g_hpA : g_hpB;
        __nv_bfloat16* hnl = (t & 1) ? g_lpA : g_lpB;
        {
            float iv = Gs[rr * 65 + jj] + Gs[32 * 65 + rr * 65 + jj] + x0;
            float fv = Gs[rr * 65 + 16 + jj] + Gs[32 * 65 + rr * 65 + 16 + jj] + x1;
            float cv = Gs[rr * 65 + 32 + jj] + Gs[32 * 65 + rr * 65 + 32 + jj] + x2;
            float ov = Gs[rr * 65 + 48 + jj] + Gs[32 * 65 + rr * 65 + 48 + jj] + x3;
            iv = 1.f / (1.f + __expf(-iv));
            fv = 1.f / (1.f + __expf(-fv));
            ov = 1.f / (1.f + __expf(-ov));
            cv = tanhf(cv);
            float c = fv * creg + iv * cv;
            creg = c;
            float h = ov * tanhf(c);
            __nv_bfloat16 vh, vl;
            bsplit(h, &vh, &vl);
            hnh[(size_t)(b0 + rr) * HH + j0 + jj] = vh;
            hnl[(size_t)(b0 + rr) * HH + j0 + jj] = vl;
            if (layer == 0) {
                g_sh[((size_t)(b0 + rr) * TT + t) * HH + j0 + jj] = vh;
                g_sl[((size_t)(b0 + rr) * TT + t) * HH + j0 + jj] = vl;
            } else if (t == TT - 1) {
                g_hfin[(size_t)(b0 + rr) * HH + j0 + jj] = h;
            }
        }
        if (t < TT - 1) grid_bar4(grp);
    }
}

// ---------------- layernorm (eps=1e-3) on g_hfin ----------------
__global__ void layernorm(const float* __restrict__ gamma, const float* __restrict__ beta) {
    const int b = blockIdx.x, tid = threadIdx.x;
    const float* __restrict__ h = &g_hfin[b * HH];
    __shared__ float red[8];
    __shared__ float bc_mu, bc_rs;
    float s = 0.f;
    for (int j = tid; j < HH; j += 256) s += h[j];
#pragma unroll
    for (int o = 16; o; o >>= 1) s += __shfl_xor_sync(0xffffffffu, s, o);
    if ((tid & 31) == 0) red[tid >> 5] = s;
    __syncthreads();
    if (tid == 0) {
        float ts = 0.f;
        for (int i = 0; i < 8; i++) ts += red[i];
        bc_mu = ts / (float)HH;
    }
    __syncthreads();
    float mu = bc_mu;
    float v = 0.f;
    for (int j = tid; j < HH; j += 256) { float dd = h[j] - mu; v += dd * dd; }
#pragma unroll
    for (int o = 16; o; o >>= 1) v += __shfl_xor_sync(0xffffffffu, v, o);
    __syncthreads();
    if ((tid & 31) == 0) red[tid >> 5] = v;
    __syncthreads();
    if (tid == 0) {
        float ts = 0.f;
        for (int i = 0; i < 8; i++) ts += red[i];
        bc_rs = rsqrtf(ts / (float)HH + 1e-3f);
    }
    __syncthreads();
    float rs = bc_rs;
    for (int j = tid; j < HH; j += 256)
        g_ln[b * HH + j] = (h[j] - mu) * rs * gamma[j] + beta[j];
}

// ---------------- dense2 + relu ----------------
__global__ void dense2(const float* __restrict__ W2, const float* __restrict__ b2) {
    const int b = blockIdx.x, c = threadIdx.x;
    const float* __restrict__ h = &g_ln[b * HH];
    float s = b2[c];
    for (int k = 0; k < HH; k++) s += h[k] * W2[k * 256 + c];
    g_d2[b * 256 + c] = fmaxf(s, 0.f);
}

// ---------------- dense3 ----------------
__global__ void dense3(const float* __restrict__ W3, const float* __restrict__ b3,
                       float* __restrict__ out) {
    const int b = blockIdx.x, tid = threadIdx.x;
    float s = g_d2[b * 256 + tid] * W3[tid];
#pragma unroll
    for (int o = 16; o; o >>= 1) s += __shfl_xor_sync(0xffffffffu, s, o);
    __shared__ float red[8];
    if ((tid & 31) == 0) red[tid >> 5] = s;
    __syncthreads();
    if (tid == 0) {
        float ts = 0.f;
        for (int i = 0; i < 8; i++) ts += red[i];
        out[b] = ts + b3[0];
    }
}

// ---------------- launch ----------------
extern "C" void kernel_launch(void* const* d_in, const int* in_sizes, int n_in,
                              void* d_out, int out_size) {
    const float* x     = (const float*)d_in[0];
    const float* W1    = (const float*)d_in[1];
    const float* b1    = (const float*)d_in[2];
    const float* Wx1   = (const float*)d_in[3];
    const float* Wh1   = (const float*)d_in[4];
    const float* bl1   = (const float*)d_in[5];
    const float* Wx2   = (const float*)d_in[6];
    const float* Wh2   = (const float*)d_in[7];
    const float* bl2   = (const float*)d_in[8];
    const float* gamma = (const float*)d_in[9];
    const float* beta  = (const float*)d_in[10];
    const float* W2    = (const float*)d_in[11];
    const float* b2    = (const float*)d_in[12];
    const float* W3    = (const float*)d_in[13];
    const float* b3    = (const float*)d_in[14];
    float* out = (float*)d_out;

    static int init_done = 0;
    if (!init_done) {
        cudaFuncSetAttribute(lstm_mma, cudaFuncAttributeMaxDynamicSharedMemorySize,
                             L_SMEM);
        cudaFuncSetAttribute(gemm_xg, cudaFuncAttributeMaxDynamicSharedMemorySize,
                             XS_SMEM);
        init_done = 1;
    }

    dense1_norm<<<(BB * TT) / 16, 256>>>(x, W1, b1);
    convW<<<(HH * G4 + 255) / 256, 256>>>(Wx1, 0);
    convW<<<(HH * G4 + 255) / 256, 256>>>(Wx2, 1);

    gemm_xg<<<dim3(G4 / 128, (BB * TT) / 128), 512, XS_SMEM>>>(0, bl1);
    zero_h<<<(BB * HH / 2 + 255) / 256, 256>>>();
    lstm_mma<<<NBLK, 512, L_SMEM>>>(Wh1, 0);

    gemm_xg<<<dim3(G4 / 128, (BB * TT) / 128), 512, XS_SMEM>>>(1, bl2);
    zero_h<<<(BB * HH / 2 + 255) / 256, 256>>>();
    lstm_mma<<<NBLK, 512, L_SMEM>>>(Wh2, 1);

    layernorm<<<BB, 256>>>(gamma, beta);
    dense2<<<BB, 256>>>(W2, b2);
    dense3<<<BB, 256>>>(W3, b3, out);
}

// round 10
// speedup vs baseline: 2.1806x; 1.0598x over previous
#include <cuda_runtime.h>
#include <cuda_bf16.h>
#include <math.h>
#include <stdint.h>

#define BB 128
#define TT 256
#define FF 64
#define HH 512
#define G4 2048
#define NBLK 128  // persistent LSTM grid

// ---------------- mma / ldmatrix / cp.async helpers (arch-generic) ----------
__device__ __forceinline__ void mma_bf16(float* d, const uint32_t* a, const uint32_t* b) {
    asm volatile(
        "mma.sync.aligned.m16n8k16.row.col.f32.bf16.bf16.f32 "
        "{%0,%1,%2,%3}, {%4,%5,%6,%7}, {%8,%9}, {%0,%1,%2,%3};"
        : "+f"(d[0]), "+f"(d[1]), "+f"(d[2]), "+f"(d[3])
        : "r"(a[0]), "r"(a[1]), "r"(a[2]), "r"(a[3]), "r"(b[0]), "r"(b[1]));
}
__device__ __forceinline__ void ldsm4(uint32_t* r, uint32_t addr) {
    asm volatile("ldmatrix.sync.aligned.m8n8.x4.shared.b16 {%0,%1,%2,%3}, [%4];"
        : "=r"(r[0]), "=r"(r[1]), "=r"(r[2]), "=r"(r[3]) : "r"(addr));
}
__device__ __forceinline__ uint32_t smem_u32(const void* p) {
    uint32_t a;
    asm("{ .reg .u64 t; cvta.to.shared.u64 t, %1; cvt.u32.u64 %0, t; }"
        : "=r"(a) : "l"(p));
    return a;
}
__device__ __forceinline__ void cp16(uint32_t dst, const void* src) {
    asm volatile("cp.async.cg.shared.global [%0], [%1], 16;"
        :: "r"(dst), "l"(src) : "memory");
}
#define CP_COMMIT() asm volatile("cp.async.commit_group;" ::: "memory")
#define CP_WAIT0()  asm volatile("cp.async.wait_group 0;" ::: "memory")
#define CP_WAIT1()  asm volatile("cp.async.wait_group 1;" ::: "memory")

__device__ __forceinline__ void bsplit(float w, __nv_bfloat16* hi, __nv_bfloat16* lo) {
    __nv_bfloat16 h = __float2bfloat16(w);
    *hi = h;
    *lo = __float2bfloat16(w - __bfloat162float(h));
}
__device__ __forceinline__ float fsigm(float x) {
    return __fdividef(1.f, 1.f + __expf(-x));
}
__device__ __forceinline__ float ftanh(float x) {
    x = fminf(fmaxf(x, -15.f), 15.f);
    float e = __expf(-2.f * x);
    return __fdividef(1.f - e, 1.f + e);
}

// ---------------- scratch ----------------
__device__ __nv_bfloat16 g_hh[BB * TT * HH], g_hl[BB * TT * HH];
__device__ __nv_bfloat16 g_sh[BB * TT * HH], g_sl[BB * TT * HH];
__device__ __nv_bfloat16 g_Wxh[2][G4 * HH], g_Wxl[2][G4 * HH];
__device__ float g_xg[(size_t)BB * TT * G4];
__device__ __nv_bfloat16 g_hpA[BB * HH], g_hpB[BB * HH];
__device__ __nv_bfloat16 g_lpA[BB * HH], g_lpB[BB * HH];
__device__ float g_hfin[BB * HH];
__device__ float g_ln[BB * HH];
__device__ float g_d2[BB * (HH / 2)];
__device__ unsigned g_cnt4[4];
__device__ unsigned g_gen4[4];

// ------- per-batch-group grid barrier (4 independent groups of 32 blocks) ---
__device__ __forceinline__ void grid_bar4(int grp) {
    __syncthreads();
    if (threadIdx.x == 0) {
        __threadfence();
        unsigned gen = *(volatile unsigned*)&g_gen4[grp];
        if (atomicAdd(&g_cnt4[grp], 1u) == 31u) {
            g_cnt4[grp] = 0u;
            __threadfence();
            atomicAdd(&g_gen4[grp], 1u);
        } else {
            while (*(volatile unsigned*)&g_gen4[grp] == gen) {}
        }
        __threadfence();
    }
    __syncthreads();
}

// ---------------- dense1 + L2-norm scale (writes bf16 splits) ---------------
__global__ void dense1_norm(const float* __restrict__ x, const float* __restrict__ W1,
                            const float* __restrict__ b1) {
    __shared__ float xs[16][FF];
    __shared__ float hs[16][HH];
    const int tid = threadIdx.x;
    const int m0 = blockIdx.x * 16;
    for (int i = tid; i < 16 * FF; i += 256)
        xs[i / FF][i % FF] = x[(m0 + i / FF) * FF + i % FF];
    __syncthreads();
    const int c0 = tid * 2;
    float a0[16], a1[16];
#pragma unroll
    for (int r = 0; r < 16; r++) { a0[r] = 0.f; a1[r] = 0.f; }
    for (int k = 0; k < FF; k++) {
        float w0 = W1[k * HH + c0], w1 = W1[k * HH + c0 + 1];
#pragma unroll
        for (int r = 0; r < 16; r++) { float xv = xs[r][k]; a0[r] += xv * w0; a1[r] += xv * w1; }
    }
    float bb0 = b1[c0], bb1 = b1[c0 + 1];
#pragma unroll
    for (int r = 0; r < 16; r++) { hs[r][c0] = a0[r] + bb0; hs[r][c0 + 1] = a1[r] + bb1; }
    __syncthreads();
    int wid = tid >> 5, lane = tid & 31;
#pragma unroll
    for (int rr = 0; rr < 2; rr++) {
        int r = wid * 2 + rr;
        float ss = 0.f;
        for (int c = lane; c < HH; c += 32) { float v = hs[r][c]; ss += v * v; }
#pragma unroll
        for (int o = 16; o; o >>= 1) ss += __shfl_xor_sync(0xffffffffu, ss, o);
        float sc = sqrtf((float)HH) / fmaxf(sqrtf(ss), 1e-12f);
        for (int c = lane; c < HH; c += 32) {
            float v = hs[r][c] * sc;
            __nv_bfloat16 vh, vl;
            bsplit(v, &vh, &vl);
            g_hh[(size_t)(m0 + r) * HH + c] = vh;
            g_hl[(size_t)(m0 + r) * HH + c] = vl;
        }
    }
}

// ---------------- Wx -> transposed bf16 splits [n][k] ----------------
__global__ void convW(const float* __restrict__ W, int layer) {
    int i = blockIdx.x * 256 + threadIdx.x;
    if (i < HH * G4) {
        int k = i / G4, n = i % G4;
        __nv_bfloat16 h_, l_;
        bsplit(W[i], &h_, &l_);
        g_Wxh[layer][(size_t)n * HH + k] = h_;
        g_Wxl[layer][(size_t)n * HH + k] = l_;
    }
}

// ---------------- xg GEMM: 256 thr, 8 warps (4m x 2n), warp 32x64 -----------
#define XS_STAGE 24576   // 4 arrays * 128 rows * 48B
#define XS_SMEM  (2 * XS_STAGE)

__global__ void __launch_bounds__(256, 2) gemm_xg(int layer, const float* __restrict__ bias) {
    const __nv_bfloat16* __restrict__ Ah = layer ? g_sh : g_hh;
    const __nv_bfloat16* __restrict__ Al = layer ? g_sl : g_hl;
    const __nv_bfloat16* __restrict__ Bh = g_Wxh[layer];
    const __nv_bfloat16* __restrict__ Bl = g_Wxl[layer];

    extern __shared__ __align__(16) uint8_t smd[];
    const int tid = threadIdx.x;
    const int lane = tid & 31, wid = tid >> 5;
    const int n0 = blockIdx.x * 128, m0 = blockIdx.y * 128;
    const int m_off = (wid >> 1) * 32, n_off = (wid & 1) * 64;
    const int lr = lane >> 2, lc = (lane & 3) * 2;

    float acc[2][8][4];
#pragma unroll
    for (int i = 0; i < 2; i++)
#pragma unroll
        for (int j = 0; j < 8; j++)
#pragma unroll
            for (int q = 0; q < 4; q++) acc[i][j][q] = 0.f;

    // copy mapping: 1024 cp16 per stage, 4 per thread
    const uint32_t smb = smem_u32(smd);
    const __nv_bfloat16* srcs[4];
    uint32_t dsts[4];
#pragma unroll
    for (int j = 0; j < 4; j++) {
        int id = tid + 256 * j;
        int arr = id >> 8, row = (id >> 1) & 127, hf = id & 1;
        const __nv_bfloat16* base =
            (arr == 0 ? Ah + (size_t)(m0 + row) * HH :
             arr == 1 ? Al + (size_t)(m0 + row) * HH :
             arr == 2 ? Bh + (size_t)(n0 + row) * HH :
                        Bl + (size_t)(n0 + row) * HH);
        srcs[j] = base + hf * 8;
        dsts[j] = smb + arr * 6144 + row * 48 + hf * 16;
    }

#pragma unroll
    for (int j = 0; j < 4; j++) cp16(dsts[j], srcs[j]);
    CP_COMMIT();

    int s = 0;
    for (int kc = 0; kc < HH; kc += 16) {
        if (kc + 16 < HH) {
#pragma unroll
            for (int j = 0; j < 4; j++) cp16(dsts[j] + (s ^ 1) * XS_STAGE, srcs[j] + kc + 16);
            CP_COMMIT();
            CP_WAIT1();
        } else {
            CP_WAIT0();
        }
        __syncthreads();
        const uint32_t sb = smb + s * XS_STAGE;

        uint32_t afh[2][4], afl[2][4];
#pragma unroll
        for (int mi = 0; mi < 2; mi++) {
            uint32_t ar = sb + (m_off + mi * 16 + (lane & 15)) * 48 + (lane >> 4) * 16;
            ldsm4(afh[mi], ar);
            ldsm4(afl[mi], ar + 6144);
        }
        uint32_t bfh[8][2], bfl[8][2];
#pragma unroll
        for (int g = 0; g < 4; g++) {
            uint32_t br = sb + 12288 + (n_off + g * 16 + (lane & 15)) * 48 + (lane >> 4) * 16;
            uint32_t tt[4];
            ldsm4(tt, br);
            bfh[2 * g][0] = tt[0]; bfh[2 * g + 1][0] = tt[1];
            bfh[2 * g][1] = tt[2]; bfh[2 * g + 1][1] = tt[3];
            ldsm4(tt, br + 6144);
            bfl[2 * g][0] = tt[0]; bfl[2 * g + 1][0] = tt[1];
            bfl[2 * g][1] = tt[2]; bfl[2 * g + 1][1] = tt[3];
        }
#pragma unroll
        for (int mi = 0; mi < 2; mi++)
#pragma unroll
            for (int nf = 0; nf < 8; nf++) {
                mma_bf16(acc[mi][nf], afh[mi], bfh[nf]);
                mma_bf16(acc[mi][nf], afh[mi], bfl[nf]);
                mma_bf16(acc[mi][nf], afl[mi], bfh[nf]);
            }
        __syncthreads();
        s ^= 1;
    }

#pragma unroll
    for (int mi = 0; mi < 2; mi++)
#pragma unroll
        for (int nf = 0; nf < 8; nf++) {
            int r = m0 + m_off + mi * 16 + lr;
            int c = n0 + n_off + nf * 8 + lc;
            float2 bv = *(const float2*)&bias[c];
            *(float2*)&g_xg[(size_t)r * G4 + c] =
                make_float2(acc[mi][nf][0] + bv.x, acc[mi][nf][1] + bv.y);
            *(float2*)&g_xg[(size_t)(r + 8) * G4 + c] =
                make_float2(acc[mi][nf][2] + bv.x, acc[mi][nf][3] + bv.y);
        }
}

// ---------------- zero initial h splits ----------------
__global__ void zero_h() {
    int i = blockIdx.x * 256 + threadIdx.x;
    if (i < BB * HH / 2) {
        ((unsigned*)g_hpA)[i] = 0u;
        ((unsigned*)g_lpA)[i] = 0u;
    }
}

// ==================== persistent mma.sync LSTM (512 thr, K-split) ===========
// 128 blocks; block = 32 batch x 64 gate-cols. Warps 0-7: K[0,256), 8-15: K[256,512).
// Each K-half warp-group loads & waits for ONLY its own half (named barrier).
#define L_BHI 0
#define L_BLO 66560
#define L_AHI 133120
#define L_ALO 166400
#define L_GS  199680
#define L_SMEM 216320

__global__ void __launch_bounds__(512, 1)
lstm_mma(const float* __restrict__ Wh, int layer) {
    extern __shared__ __align__(16) uint8_t sm[];
    const int tid = threadIdx.x, lane = tid & 31, wid = tid >> 5;
    const int grp = blockIdx.x >> 5;
    const int b0 = grp * 32;
    const int j0 = (blockIdx.x & 31) * 16;
    const int kh = wid >> 3;                 // K half
    const int wq = wid & 7;
    const int m_off = (wq >> 2) * 16, n_off = (wq & 3) * 16;
    const int lr = lane >> 2, lc = (lane & 3) * 2;

    // Wh slice -> bf16 hi/lo, [n][k] padded rows (520 elems = 1040B)
    for (int i = tid; i < 64 * HH; i += 512) {
        int n = i & 63, k = i >> 6;
        float w = Wh[k * G4 + (n >> 4) * HH + j0 + (n & 15)];
        __nv_bfloat16 h_, l_;
        bsplit(w, &h_, &l_);
        *(__nv_bfloat16*)(sm + L_BHI + ((size_t)n * 520 + k) * 2) = h_;
        *(__nv_bfloat16*)(sm + L_BLO + ((size_t)n * 520 + k) * 2) = l_;
    }
    __syncthreads();

    float* Gs = (float*)(sm + L_GS);         // [2][32][65]
    const uint32_t smb = smem_u32(sm);
    const int rr = tid >> 4, jj = tid & 15;  // gate-math element (1/thread)
    const int tidl = tid & 255;
    const int kbase = kh * 256;
    float creg = 0.f;

    const uint32_t rAh = smb + L_AHI + (m_off + (lane & 15)) * 1040 + (lane >> 4) * 16 + kh * 512;
    const uint32_t rAl = smb + L_ALO + (m_off + (lane & 15)) * 1040 + (lane >> 4) * 16 + kh * 512;
    const uint32_t rBh = smb + L_BHI + (n_off + (lane & 15)) * 1040 + (lane >> 4) * 16 + kh * 512;
    const uint32_t rBl = smb + L_BLO + (n_off + (lane & 15)) * 1040 + (lane >> 4) * 16 + kh * 512;

    for (int t = 0; t < TT; t++) {
        const __nv_bfloat16* hph = (t & 1) ? g_hpB : g_hpA;
        const __nv_bfloat16* hpl = (t & 1) ? g_lpB : g_lpA;

        // xg prefetch (1 element's 4 gates per thread)
        const float* xb = g_xg + ((size_t)(b0 + rr) * TT + t) * G4 + j0 + jj;
        float x0 = xb[0], x1 = xb[512], x2 = xb[1024], x3 = xb[1536];

        // each K-half warp-group loads ONLY its own half of the h tile
#pragma unroll
        for (int idx = tidl; idx < 1024; idx += 256) {
            int row = idx >> 5, k8 = (idx & 31) * 8 + kbase;
            cp16(smb + L_AHI + row * 1040 + k8 * 2, hph + (size_t)(b0 + row) * HH + k8);
            cp16(smb + L_ALO + row * 1040 + k8 * 2, hpl + (size_t)(b0 + row) * HH + k8);
        }
        CP_COMMIT();
        CP_WAIT0();
        asm volatile("bar.sync %0, 256;" :: "r"(4 + kh) : "memory");

        float acc[2][4] = {{0.f, 0.f, 0.f, 0.f}, {0.f, 0.f, 0.f, 0.f}};
#pragma unroll 2
        for (int kk = 0; kk < 256; kk += 16) {
            uint32_t ah[4], al[4], tb[4];
            uint32_t bh0[2], bh1[2], bl0[2], bl1[2];
            ldsm4(ah, rAh + kk * 2);
            ldsm4(al, rAl + kk * 2);
            ldsm4(tb, rBh + kk * 2);
            bh0[0] = tb[0]; bh1[0] = tb[1]; bh0[1] = tb[2]; bh1[1] = tb[3];
            ldsm4(tb, rBl + kk * 2);
            bl0[0] = tb[0]; bl1[0] = tb[1]; bl0[1] = tb[2]; bl1[1] = tb[3];
            mma_bf16(acc[0], ah, bh0);
            mma_bf16(acc[0], ah, bl0);
            mma_bf16(acc[0], al, bh0);
            mma_bf16(acc[1], ah, bh1);
            mma_bf16(acc[1], ah, bl1);
            mma_bf16(acc[1], al, bh1);
        }
        {
            float* Gk = Gs + kh * (32 * 65);
#pragma unroll
            for (int nf = 0; nf < 2; nf++) {
                int r = m_off + lr, c = n_off + nf * 8 + lc;
                Gk[r * 65 + c] = acc[nf][0];
                Gk[r * 65 + c + 1] = acc[nf][1];
                Gk[(r + 8) * 65 + c] = acc[nf][2];
                Gk[(r + 8) * 65 + c + 1] = acc[nf][3];
            }
        }
        __syncthreads();

        __nv_bfloat16* hnh = (t & 1) ? g_hpA : g_hpB;
        __nv_bfloat16* hnl = (t & 1) ? g_lpA : g_lpB;
        {
            float iv = Gs[rr * 65 + jj] + Gs[32 * 65 + rr * 65 + jj] + x0;
            float fv = Gs[rr * 65 + 16 + jj] + Gs[32 * 65 + rr * 65 + 16 + jj] + x1;
            float cv = Gs[rr * 65 + 32 + jj] + Gs[32 * 65 + rr * 65 + 32 + jj] + x2;
            float ov = Gs[rr * 65 + 48 + jj] + Gs[32 * 65 + rr * 65 + 48 + jj] + x3;
            iv = fsigm(iv);
            fv = fsigm(fv);
            ov = fsigm(ov);
            cv = ftanh(cv);
            float c = fv * creg + iv * cv;
            creg = c;
            float h = ov * ftanh(c);
            __nv_bfloat16 vh, vl;
            bsplit(h, &vh, &vl);
            hnh[(size_t)(b0 + rr) * HH + j0 + jj] = vh;
            hnl[(size_t)(b0 + rr) * HH + j0 + jj] = vl;
            if (layer == 0) {
                g_sh[((size_t)(b0 + rr) * TT + t) * HH + j0 + jj] = vh;
                g_sl[((size_t)(b0 + rr) * TT + t) * HH + j0 + jj] = vl;
            } else if (t == TT - 1) {
                g_hfin[(size_t)(b0 + rr) * HH + j0 + jj] = h;
            }
        }
        if (t < TT - 1) grid_bar4(grp);
    }
}

// ---------------- layernorm (eps=1e-3) on g_hfin ----------------
__global__ void layernorm(const float* __restrict__ gamma, const float* __restrict__ beta) {
    const int b = blockIdx.x, tid = threadIdx.x;
    const float* __restrict__ h = &g_hfin[b * HH];
    __shared__ float red[8];
    __shared__ float bc_mu, bc_rs;
    float s = 0.f;
    for (int j = tid; j < HH; j += 256) s += h[j];
#pragma unroll
    for (int o = 16; o; o >>= 1) s += __shfl_xor_sync(0xffffffffu, s, o);
    if ((tid & 31) == 0) red[tid >> 5] = s;
    __syncthreads();
    if (tid == 0) {
        float ts = 0.f;
        for (int i = 0; i < 8; i++) ts += red[i];
        bc_mu = ts / (float)HH;
    }
    __syncthreads();
    float mu = bc_mu;
    float v = 0.f;
    for (int j = tid; j < HH; j += 256) { float dd = h[j] - mu; v += dd * dd; }
#pragma unroll
    for (int o = 16; o; o >>= 1) v += __shfl_xor_sync(0xffffffffu, v, o);
    __syncthreads();
    if ((tid & 31) == 0) red[tid >> 5] = v;
    __syncthreads();
    if (tid == 0) {
        float ts = 0.f;
        for (int i = 0; i < 8; i++) ts += red[i];
        bc_rs = rsqrtf(ts / (float)HH + 1e-3f);
    }
    __syncthreads();
    float rs = bc_rs;
    for (int j = tid; j < HH; j += 256)
        g_ln[b * HH + j] = (h[j] - mu) * rs * gamma[j] + beta[j];
}

// ---------------- dense2 + relu ----------------
__global__ void dense2(const float* __restrict__ W2, const float* __restrict__ b2) {
    const int b = blockIdx.x, c = threadIdx.x;
    const float* __restrict__ h = &g_ln[b * HH];
    float s = b2[c];
    for (int k = 0; k < HH; k++) s += h[k] * W2[k * 256 + c];
    g_d2[b * 256 + c] = fmaxf(s, 0.f);
}

// ---------------- dense3 ----------------
__global__ void dense3(const float* __restrict__ W3, const float* __restrict__ b3,
                       float* __restrict__ out) {
    const int b = blockIdx.x, tid = threadIdx.x;
    float s = g_d2[b * 256 + tid] * W3[tid];
#pragma unroll
    for (int o = 16; o; o >>= 1) s += __shfl_xor_sync(0xffffffffu, s, o);
    __shared__ float red[8];
    if ((tid & 31) == 0) red[tid >> 5] = s;
    __syncthreads();
    if (tid == 0) {
        float ts = 0.f;
        for (int i = 0; i < 8; i++) ts += red[i];
        out[b] = ts + b3[0];
    }
}

// ---------------- launch ----------------
extern "C" void kernel_launch(void* const* d_in, const int* in_sizes, int n_in,
                              void* d_out, int out_size) {
    const float* x     = (const float*)d_in[0];
    const float* W1    = (const float*)d_in[1];
    const float* b1    = (const float*)d_in[2];
    const float* Wx1   = (const float*)d_in[3];
    const float* Wh1   = (const float*)d_in[4];
    const float* bl1   = (const float*)d_in[5];
    const float* Wx2   = (const float*)d_in[6];
    const float* Wh2   = (const float*)d_in[7];
    const float* bl2   = (const float*)d_in[8];
    const float* gamma = (const float*)d_in[9];
    const float* beta  = (const float*)d_in[10];
    const float* W2    = (const float*)d_in[11];
    const float* b2    = (const float*)d_in[12];
    const float* W3    = (const float*)d_in[13];
    const float* b3    = (const float*)d_in[14];
    float* out = (float*)d_out;

    static int init_done = 0;
    if (!init_done) {
        cudaFuncSetAttribute(lstm_mma, cudaFuncAttributeMaxDynamicSharedMemorySize,
                             L_SMEM);
        cudaFuncSetAttribute(gemm_xg, cudaFuncAttributeMaxDynamicSharedMemorySize,
                             XS_SMEM);
        init_done = 1;
    }

    dense1_norm<<<(BB * TT) / 16, 256>>>(x, W1, b1);
    convW<<<(HH * G4 + 255) / 256, 256>>>(Wx1, 0);
    convW<<<(HH * G4 + 255) / 256, 256>>>(Wx2, 1);

    gemm_xg<<<dim3(G4 / 128, (BB * TT) / 128), 256, XS_SMEM>>>(0, bl1);
    zero_h<<<(BB * HH / 2 + 255) / 256, 256>>>();
    lstm_mma<<<NBLK, 512, L_SMEM>>>(Wh1, 0);

    gemm_xg<<<dim3(G4 / 128, (BB * TT) / 128), 256, XS_SMEM>>>(1, bl2);
    zero_h<<<(BB * HH / 2 + 255) / 256, 256>>>();
    lstm_mma<<<NBLK, 512, L_SMEM>>>(Wh2, 1);

    layernorm<<<BB, 256>>>(gamma, beta);
    dense2<<<BB, 256>>>(W2, b2);
    dense3<<<BB, 256>>>(W3, b3, out);
}

// round 11
// speedup vs baseline: 2.3255x; 1.0665x over previous
#include <cuda_runtime.h>
#include <cuda_bf16.h>
#include <math.h>
#include <stdint.h>

#define BB 128
#define TT 256
#define FF 64
#define HH 512
#define G4 2048
#define NBLK 128  // persistent LSTM grid

// ---------------- mma / ldmatrix / cp.async helpers (arch-generic) ----------
__device__ __forceinline__ void mma_bf16(float* d, const uint32_t* a, const uint32_t* b) {
    asm volatile(
        "mma.sync.aligned.m16n8k16.row.col.f32.bf16.bf16.f32 "
        "{%0,%1,%2,%3}, {%4,%5,%6,%7}, {%8,%9}, {%0,%1,%2,%3};"
        : "+f"(d[0]), "+f"(d[1]), "+f"(d[2]), "+f"(d[3])
        : "r"(a[0]), "r"(a[1]), "r"(a[2]), "r"(a[3]), "r"(b[0]), "r"(b[1]));
}
__device__ __forceinline__ void ldsm4(uint32_t* r, uint32_t addr) {
    asm volatile("ldmatrix.sync.aligned.m8n8.x4.shared.b16 {%0,%1,%2,%3}, [%4];"
        : "=r"(r[0]), "=r"(r[1]), "=r"(r[2]), "=r"(r[3]) : "r"(addr));
}
__device__ __forceinline__ uint32_t smem_u32(const void* p) {
    uint32_t a;
    asm("{ .reg .u64 t; cvta.to.shared.u64 t, %1; cvt.u32.u64 %0, t; }"
        : "=r"(a) : "l"(p));
    return a;
}
__device__ __forceinline__ void cp16(uint32_t dst, const void* src) {
    asm volatile("cp.async.cg.shared.global [%0], [%1], 16;"
        :: "r"(dst), "l"(src) : "memory");
}
#define CP_COMMIT() asm volatile("cp.async.commit_group;" ::: "memory")
#define CP_WAIT0()  asm volatile("cp.async.wait_group 0;" ::: "memory")
#define CP_WAIT1()  asm volatile("cp.async.wait_group 1;" ::: "memory")

__device__ __forceinline__ void bsplit(float w, __nv_bfloat16* hi, __nv_bfloat16* lo) {
    __nv_bfloat16 h = __float2bfloat16(w);
    *hi = h;
    *lo = __float2bfloat16(w - __bfloat162float(h));
}
__device__ __forceinline__ float fsigm(float x) {
    return __fdividef(1.f, 1.f + __expf(-x));
}
__device__ __forceinline__ float ftanh(float x) {
    x = fminf(fmaxf(x, -15.f), 15.f);
    float e = __expf(-2.f * x);
    return __fdividef(1.f - e, 1.f + e);
}

// ---------------- scratch ----------------
__device__ __nv_bfloat16 g_hh[BB * TT * HH], g_hl[BB * TT * HH];
__device__ __nv_bfloat16 g_sh[BB * TT * HH], g_sl[BB * TT * HH];
__device__ __nv_bfloat16 g_Wxh[2][G4 * HH], g_Wxl[2][G4 * HH];
__device__ float g_xg[(size_t)BB * TT * G4];
__device__ __nv_bfloat16 g_hpA[BB * HH], g_hpB[BB * HH];
__device__ __nv_bfloat16 g_lpA[BB * HH], g_lpB[BB * HH];
__device__ float g_hfin[BB * HH];
__device__ float g_ln[BB * HH];
__device__ float g_d2[BB * (HH / 2)];
__device__ unsigned g_cnt4[4];
__device__ unsigned g_gen4[4];

// ------- per-batch-group grid barrier: release-arrive / acquire-spin --------
__device__ __forceinline__ void grid_bar4(int grp) {
    __syncthreads();
    if (threadIdx.x == 0) {
        unsigned* cp = &g_cnt4[grp];
        unsigned* gp = &g_gen4[grp];
        unsigned gen;
        asm volatile("ld.acquire.gpu.u32 %0, [%1];" : "=r"(gen) : "l"(gp));
        unsigned old;
        asm volatile("atom.add.release.gpu.u32 %0, [%1], 1;" : "=r"(old) : "l"(cp) : "memory");
        if (old == 31u) {
            asm volatile("st.relaxed.gpu.u32 [%0], 0;" :: "l"(cp) : "memory");
            asm volatile("red.add.release.gpu.u32 [%0], 1;" :: "l"(gp) : "memory");
        } else {
            unsigned g2;
            do {
                asm volatile("ld.acquire.gpu.u32 %0, [%1];" : "=r"(g2) : "l"(gp));
            } while (g2 == gen);
        }
    }
    __syncthreads();
}

// ---------------- dense1 + L2-norm scale (writes bf16 splits) ---------------
__global__ void dense1_norm(const float* __restrict__ x, const float* __restrict__ W1,
                            const float* __restrict__ b1) {
    __shared__ float xs[16][FF];
    __shared__ float hs[16][HH];
    const int tid = threadIdx.x;
    const int m0 = blockIdx.x * 16;
    for (int i = tid; i < 16 * FF; i += 256)
        xs[i / FF][i % FF] = x[(m0 + i / FF) * FF + i % FF];
    __syncthreads();
    const int c0 = tid * 2;
    float a0[16], a1[16];
#pragma unroll
    for (int r = 0; r < 16; r++) { a0[r] = 0.f; a1[r] = 0.f; }
    for (int k = 0; k < FF; k++) {
        float w0 = W1[k * HH + c0], w1 = W1[k * HH + c0 + 1];
#pragma unroll
        for (int r = 0; r < 16; r++) { float xv = xs[r][k]; a0[r] += xv * w0; a1[r] += xv * w1; }
    }
    float bb0 = b1[c0], bb1 = b1[c0 + 1];
#pragma unroll
    for (int r = 0; r < 16; r++) { hs[r][c0] = a0[r] + bb0; hs[r][c0 + 1] = a1[r] + bb1; }
    __syncthreads();
    int wid = tid >> 5, lane = tid & 31;
#pragma unroll
    for (int rr = 0; rr < 2; rr++) {
        int r = wid * 2 + rr;
        float ss = 0.f;
        for (int c = lane; c < HH; c += 32) { float v = hs[r][c]; ss += v * v; }
#pragma unroll
        for (int o = 16; o; o >>= 1) ss += __shfl_xor_sync(0xffffffffu, ss, o);
        float sc = sqrtf((float)HH) / fmaxf(sqrtf(ss), 1e-12f);
        for (int c = lane; c < HH; c += 32) {
            float v = hs[r][c] * sc;
            __nv_bfloat16 vh, vl;
            bsplit(v, &vh, &vl);
            g_hh[(size_t)(m0 + r) * HH + c] = vh;
            g_hl[(size_t)(m0 + r) * HH + c] = vl;
        }
    }
}

// ---------------- Wx -> transposed bf16 splits [n][k] ----------------
__global__ void convW(const float* __restrict__ W, int layer) {
    int i = blockIdx.x * 256 + threadIdx.x;
    if (i < HH * G4) {
        int k = i / G4, n = i % G4;
        __nv_bfloat16 h_, l_;
        bsplit(W[i], &h_, &l_);
        g_Wxh[layer][(size_t)n * HH + k] = h_;
        g_Wxl[layer][(size_t)n * HH + k] = l_;
    }
}

// ---------------- xg GEMM: 256 thr, 8 warps (4m x 2n), warp 32x64, Kc=32 ----
#define XS_ROW   80                    // 32 bf16 (64B) + 16B pad
#define XS_ARR   (128 * XS_ROW)        // 10240
#define XS_STAGE (4 * XS_ARR)          // 40960
#define XS_SMEM  (2 * XS_STAGE)        // 81920

__global__ void __launch_bounds__(256, 2) gemm_xg(int layer, const float* __restrict__ bias) {
    const __nv_bfloat16* __restrict__ Ah = layer ? g_sh : g_hh;
    const __nv_bfloat16* __restrict__ Al = layer ? g_sl : g_hl;
    const __nv_bfloat16* __restrict__ Bh = g_Wxh[layer];
    const __nv_bfloat16* __restrict__ Bl = g_Wxl[layer];

    extern __shared__ __align__(16) uint8_t smd[];
    const int tid = threadIdx.x;
    const int lane = tid & 31, wid = tid >> 5;
    const int n0 = blockIdx.x * 128, m0 = blockIdx.y * 128;
    const int m_off = (wid >> 1) * 32, n_off = (wid & 1) * 64;
    const int lr = lane >> 2, lc = (lane & 3) * 2;

    float acc[2][8][4];
#pragma unroll
    for (int i = 0; i < 2; i++)
#pragma unroll
        for (int j = 0; j < 8; j++)
#pragma unroll
            for (int q = 0; q < 4; q++) acc[i][j][q] = 0.f;

    // copy mapping: 2048 cp16 per Kc=32 stage, 8 per thread
    const uint32_t smb = smem_u32(smd);
    const __nv_bfloat16* srcs[8];
    uint32_t dsts[8];
#pragma unroll
    for (int j = 0; j < 8; j++) {
        int id = tid + 256 * j;
        int arr = id >> 9, row = (id >> 2) & 127, seg = id & 3;
        const __nv_bfloat16* base =
            (arr == 0 ? Ah + (size_t)(m0 + row) * HH :
             arr == 1 ? Al + (size_t)(m0 + row) * HH :
             arr == 2 ? Bh + (size_t)(n0 + row) * HH :
                        Bl + (size_t)(n0 + row) * HH);
        srcs[j] = base + seg * 8;
        dsts[j] = smb + arr * XS_ARR + row * XS_ROW + seg * 16;
    }

#pragma unroll
    for (int j = 0; j < 8; j++) cp16(dsts[j], srcs[j]);
    CP_COMMIT();

    int s = 0;
    for (int kc = 0; kc < HH; kc += 32) {
        if (kc + 32 < HH) {
#pragma unroll
            for (int j = 0; j < 8; j++) cp16(dsts[j] + (s ^ 1) * XS_STAGE, srcs[j] + kc + 32);
            CP_COMMIT();
            CP_WAIT1();
        } else {
            CP_WAIT0();
        }
        __syncthreads();
        const uint32_t sb = smb + s * XS_STAGE;

#pragma unroll
        for (int ks = 0; ks < 32; ks += 16) {
            uint32_t afh[2][4], afl[2][4];
#pragma unroll
            for (int mi = 0; mi < 2; mi++) {
                uint32_t ar = sb + (m_off + mi * 16 + (lane & 15)) * XS_ROW +
                              ks * 2 + (lane >> 4) * 16;
                ldsm4(afh[mi], ar);
                ldsm4(afl[mi], ar + XS_ARR);
            }
            uint32_t bfh[8][2], bfl[8][2];
#pragma unroll
            for (int g = 0; g < 4; g++) {
                uint32_t br = sb + 2 * XS_ARR + (n_off + g * 16 + (lane & 15)) * XS_ROW +
                              ks * 2 + (lane >> 4) * 16;
                uint32_t tt[4];
                ldsm4(tt, br);
                bfh[2 * g][0] = tt[0]; bfh[2 * g + 1][0] = tt[1];
                bfh[2 * g][1] = tt[2]; bfh[2 * g + 1][1] = tt[3];
                ldsm4(tt, br + XS_ARR);
                bfl[2 * g][0] = tt[0]; bfl[2 * g + 1][0] = tt[1];
                bfl[2 * g][1] = tt[2]; bfl[2 * g + 1][1] = tt[3];
            }
#pragma unroll
            for (int mi = 0; mi < 2; mi++)
#pragma unroll
                for (int nf = 0; nf < 8; nf++) {
                    mma_bf16(acc[mi][nf], afh[mi], bfh[nf]);
                    mma_bf16(acc[mi][nf], afh[mi], bfl[nf]);
                    mma_bf16(acc[mi][nf], afl[mi], bfh[nf]);
                }
        }
        __syncthreads();
        s ^= 1;
    }

#pragma unroll
    for (int mi = 0; mi < 2; mi++)
#pragma unroll
        for (int nf = 0; nf < 8; nf++) {
            int r = m0 + m_off + mi * 16 + lr;
            int c = n0 + n_off + nf * 8 + lc;
            float2 bv = *(const float2*)&bias[c];
            *(float2*)&g_xg[(size_t)r * G4 + c] =
                make_float2(acc[mi][nf][0] + bv.x, acc[mi][nf][1] + bv.y);
            *(float2*)&g_xg[(size_t)(r + 8) * G4 + c] =
                make_float2(acc[mi][nf][2] + bv.x, acc[mi][nf][3] + bv.y);
        }
}

// ---------------- zero initial h splits ----------------
__global__ void zero_h() {
    int i = blockIdx.x * 256 + threadIdx.x;
    if (i < BB * HH / 2) {
        ((unsigned*)g_hpA)[i] = 0u;
        ((unsigned*)g_lpA)[i] = 0u;
    }
}

// ==================== persistent mma.sync LSTM (512 thr, K-split) ===========
#define L_BHI 0
#define L_BLO 66560
#define L_AHI 133120
#define L_ALO 166400
#define L_GS  199680
#define L_SMEM 216320

__global__ void __launch_bounds__(512, 1)
lstm_mma(const float* __restrict__ Wh, int layer) {
    extern __shared__ __align__(16) uint8_t sm[];
    const int tid = threadIdx.x, lane = tid & 31, wid = tid >> 5;
    const int grp = blockIdx.x >> 5;
    const int b0 = grp * 32;
    const int j0 = (blockIdx.x & 31) * 16;
    const int kh = wid >> 3;
    const int wq = wid & 7;
    const int m_off = (wq >> 2) * 16, n_off = (wq & 3) * 16;
    const int lr = lane >> 2, lc = (lane & 3) * 2;

    for (int i = tid; i < 64 * HH; i += 512) {
        int n = i & 63, k = i >> 6;
        float w = Wh[k * G4 + (n >> 4) * HH + j0 + (n & 15)];
        __nv_bfloat16 h_, l_;
        bsplit(w, &h_, &l_);
        *(__nv_bfloat16*)(sm + L_BHI + ((size_t)n * 520 + k) * 2) = h_;
        *(__nv_bfloat16*)(sm + L_BLO + ((size_t)n * 520 + k) * 2) = l_;
    }
    __syncthreads();

    float* Gs = (float*)(sm + L_GS);
    const uint32_t smb = smem_u32(sm);
    const int rr = tid >> 4, jj = tid & 15;
    const int tidl = tid & 255;
    const int kbase = kh * 256;
    float creg = 0.f;

    const uint32_t rAh = smb + L_AHI + (m_off + (lane & 15)) * 1040 + (lane >> 4) * 16 + kh * 512;
    const uint32_t rAl = smb + L_ALO + (m_off + (lane & 15)) * 1040 + (lane >> 4) * 16 + kh * 512;
    const uint32_t rBh = smb + L_BHI + (n_off + (lane & 15)) * 1040 + (lane >> 4) * 16 + kh * 512;
    const uint32_t rBl = smb + L_BLO + (n_off + (lane & 15)) * 1040 + (lane >> 4) * 16 + kh * 512;

    for (int t = 0; t < TT; t++) {
        const __nv_bfloat16* hph = (t & 1) ? g_hpB : g_hpA;
        const __nv_bfloat16* hpl = (t & 1) ? g_lpB : g_lpA;

        const float* xb = g_xg + ((size_t)(b0 + rr) * TT + t) * G4 + j0 + jj;
        float x0 = xb[0], x1 = xb[512], x2 = xb[1024], x3 = xb[1536];

#pragma unroll
        for (int idx = tidl; idx < 1024; idx += 256) {
            int row = idx >> 5, k8 = (idx & 31) * 8 + kbase;
            cp16(smb + L_AHI + row * 1040 + k8 * 2, hph + (size_t)(b0 + row) * HH + k8);
            cp16(smb + L_ALO + row * 1040 + k8 * 2, hpl + (size_t)(b0 + row) * HH + k8);
        }
        CP_COMMIT();
        CP_WAIT0();
        asm volatile("bar.sync %0, 256;" :: "r"(4 + kh) : "memory");

        float acc[2][4] = {{0.f, 0.f, 0.f, 0.f}, {0.f, 0.f, 0.f, 0.f}};
#pragma unroll 2
        for (int kk = 0; kk < 256; kk += 16) {
            uint32_t ah[4], al[4], tb[4];
            uint32_t bh0[2], bh1[2], bl0[2], bl1[2];
            ldsm4(ah, rAh + kk * 2);
            ldsm4(al, rAl + kk * 2);
            ldsm4(tb, rBh + kk * 2);
            bh0[0] = tb[0]; bh1[0] = tb[1]; bh0[1] = tb[2]; bh1[1] = tb[3];
            ldsm4(tb, rBl + kk * 2);
            bl0[0] = tb[0]; bl1[0] = tb[1]; bl0[1] = tb[2]; bl1[1] = tb[3];
            mma_bf16(acc[0], ah, bh0);
            mma_bf16(acc[0], ah, bl0);
            mma_bf16(acc[0], al, bh0);
            mma_bf16(acc[1], ah, bh1);
            mma_bf16(acc[1], ah, bl1);
            mma_bf16(acc[1], al, bh1);
        }
        {
            float* Gk = Gs + kh * (32 * 65);
#pragma unroll
            for (int nf = 0; nf < 2; nf++) {
                int r = m_off + lr, c = n_off + nf * 8 + lc;
                Gk[r * 65 + c] = acc[nf][0];
                Gk[r * 65 + c + 1] = acc[nf][1];
                Gk[(r + 8) * 65 + c] = acc[nf][2];
                Gk[(r + 8) * 65 + c + 1] = acc[nf][3];
            }
        }
        __syncthreads();

        __nv_bfloat16* hnh = (t & 1) ? g_hpA : g_hpB;
        __nv_bfloat16* hnl = (t & 1) ? g_lpA : g_lpB;
        {
            float iv = Gs[rr * 65 + jj] + Gs[32 * 65 + rr * 65 + jj] + x0;
            float fv = Gs[rr * 65 + 16 + jj] + Gs[32 * 65 + rr * 65 + 16 + jj] + x1;
            float cv = Gs[rr * 65 + 32 + jj] + Gs[32 * 65 + rr * 65 + 32 + jj] + x2;
            float ov = Gs[rr * 65 + 48 + jj] + Gs[32 * 65 + rr * 65 + 48 + jj] + x3;
            iv = fsigm(iv);
            fv = fsigm(fv);
            ov = fsigm(ov);
            cv = ftanh(cv);
            float c = fv * creg + iv * cv;
            creg = c;
            float h = ov * ftanh(c);
            __nv_bfloat16 vh, vl;
            bsplit(h, &vh, &vl);
            hnh[(size_t)(b0 + rr) * HH + j0 + jj] = vh;
            hnl[(size_t)(b0 + rr) * HH + j0 + jj] = vl;
            if (layer == 0) {
                g_sh[((size_t)(b0 + rr) * TT + t) * HH + j0 + jj] = vh;
                g_sl[((size_t)(b0 + rr) * TT + t) * HH + j0 + jj] = vl;
            } else if (t == TT - 1) {
                g_hfin[(size_t)(b0 + rr) * HH + j0 + jj] = h;
            }
        }
        if (t < TT - 1) grid_bar4(grp);
    }
}

// ---------------- layernorm (eps=1e-3) on g_hfin ----------------
__global__ void layernorm(const float* __restrict__ gamma, const float* __restrict__ beta) {
    const int b = blockIdx.x, tid = threadIdx.x;
    const float* __restrict__ h = &g_hfin[b * HH];
    __shared__ float red[8];
    __shared__ float bc_mu, bc_rs;
    float s = 0.f;
    for (int j = tid; j < HH; j += 256) s += h[j];
#pragma unroll
    for (int o = 16; o; o >>= 1) s += __shfl_xor_sync(0xffffffffu, s, o);
    if ((tid & 31) == 0) red[tid >> 5] = s;
    __syncthreads();
    if (tid == 0) {
        float ts = 0.f;
        for (int i = 0; i < 8; i++) ts += red[i];
        bc_mu = ts / (float)HH;
    }
    __syncthreads();
    float mu = bc_mu;
    float v = 0.f;
    for (int j = tid; j < HH; j += 256) { float dd = h[j] - mu; v += dd * dd; }
#pragma unroll
    for (int o = 16; o; o >>= 1) v += __shfl_xor_sync(0xffffffffu, v, o);
    __syncthreads();
    if ((tid & 31) == 0) red[tid >> 5] = v;
    __syncthreads();
    if (tid == 0) {
        float ts = 0.f;
        for (int i = 0; i < 8; i++) ts += red[i];
        bc_rs = rsqrtf(ts / (float)HH + 1e-3f);
    }
    __syncthreads();
    float rs = bc_rs;
    for (int j = tid; j < HH; j += 256)
        g_ln[b * HH + j] = (h[j] - mu) * rs * gamma[j] + beta[j];
}

// ---------------- dense2 + relu ----------------
__global__ void dense2(const float* __restrict__ W2, const float* __restrict__ b2) {
    const int b = blockIdx.x, c = threadIdx.x;
    const float* __restrict__ h = &g_ln[b * HH];
    float s = b2[c];
    for (int k = 0; k < HH; k++) s += h[k] * W2[k * 256 + c];
    g_d2[b * 256 + c] = fmaxf(s, 0.f);
}

// ---------------- dense3 ----------------
__global__ void dense3(const float* __restrict__ W3, const float* __restrict__ b3,
                       float* __restrict__ out) {
    const int b = blockIdx.x, tid = threadIdx.x;
    float s = g_d2[b * 256 + tid] * W3[tid];
#pragma unroll
    for (int o = 16; o; o >>= 1) s += __shfl_xor_sync(0xffffffffu, s, o);
    __shared__ float red[8];
    if ((tid & 31) == 0) red[tid >> 5] = s;
    __syncthreads();
    if (tid == 0) {
        float ts = 0.f;
        for (int i = 0; i < 8; i++) ts += red[i];
        out[b] = ts + b3[0];
    }
}

// ---------------- launch ----------------
extern "C" void kernel_launch(void* const* d_in, const int* in_sizes, int n_in,
                              void* d_out, int out_size) {
    const float* x     = (const float*)d_in[0];
    const float* W1    = (const float*)d_in[1];
    const float* b1    = (const float*)d_in[2];
    const float* Wx1   = (const float*)d_in[3];
    const float* Wh1   = (const float*)d_in[4];
    const float* bl1   = (const float*)d_in[5];
    const float* Wx2   = (const float*)d_in[6];
    const float* Wh2   = (const float*)d_in[7];
    const float* bl2   = (const float*)d_in[8];
    const float* gamma = (const float*)d_in[9];
    const float* beta  = (const float*)d_in[10];
    const float* W2    = (const float*)d_in[11];
    const float* b2    = (const float*)d_in[12];
    const float* W3    = (const float*)d_in[13];
    const float* b3    = (const float*)d_in[14];
    float* out = (float*)d_out;

    static int init_done = 0;
    if (!init_done) {
        cudaFuncSetAttribute(lstm_mma, cudaFuncAttributeMaxDynamicSharedMemorySize,
                             L_SMEM);
        cudaFuncSetAttribute(gemm_xg, cudaFuncAttributeMaxDynamicSharedMemorySize,
                             XS_SMEM);
        init_done = 1;
    }

    dense1_norm<<<(BB * TT) / 16, 256>>>(x, W1, b1);
    convW<<<(HH * G4 + 255) / 256, 256>>>(Wx1, 0);
    convW<<<(HH * G4 + 255) / 256, 256>>>(Wx2, 1);

    gemm_xg<<<dim3(G4 / 128, (BB * TT) / 128), 256, XS_SMEM>>>(0, bl1);
    zero_h<<<(BB * HH / 2 + 255) / 256, 256>>>();
    lstm_mma<<<NBLK, 512, L_SMEM>>>(Wh1, 0);

    gemm_xg<<<dim3(G4 / 128, (BB * TT) / 128), 256, XS_SMEM>>>(1, bl2);
    zero_h<<<(BB * HH / 2 + 255) / 256, 256>>>();
    lstm_mma<<<NBLK, 512, L_SMEM>>>(Wh2, 1);

    layernorm<<<BB, 256>>>(gamma, beta);
    dense2<<<BB, 256>>>(W2, b2);
    dense3<<<BB, 256>>>(W3, b3, out);
}